// round 3
// baseline (speedup 1.0000x reference)
#include <cuda_runtime.h>
#include <cuda_bf16.h>

// ---------------------------------------------------------------------------
// BaseGNN: 3-layer GCN, N=100000 nodes, E=1.6M edges, B=64 graphs
// Strategy: build CSR by dst once per call (no float atomics in convs),
// fp32 register-tiled GEMMs, warp-per-node gather aggregation (L2-resident),
// fused bias+residual+LN+ReLU, segment-aware pooling.
// NOTE: edge_index / batch are int32 (JAX x64 disabled -> int64 request
// silently becomes int32).
// ---------------------------------------------------------------------------

#define N_MAX 100000
#define E_MAX 1600000
#define NB    64
#define HID   128
#define OUTD  256

__device__ int   g_deg[N_MAX];
__device__ int   g_rowptr[N_MAX + 1];
__device__ int   g_cursor[N_MAX];
__device__ int   g_csr_src[E_MAX];
__device__ float g_csr_norm[E_MAX];
__device__ float g_dinv[N_MAX];
__device__ float g_bufA[(size_t)N_MAX * HID];
__device__ float g_bufB[(size_t)N_MAX * HID];
__device__ float g_res [(size_t)N_MAX * HID];
__device__ float g_hbuf[(size_t)N_MAX * HID];
__device__ float g_p256a[(size_t)N_MAX * OUTD];
__device__ float g_p256b[(size_t)N_MAX * OUTD];
__device__ int   g_cnt[NB];

// ---------------------------------------------------------------------------
__global__ void zero_kernel(int n, float* out) {
    int i = blockIdx.x * blockDim.x + threadIdx.x;
    if (i < n)        g_deg[i] = 0;
    if (i < NB)       g_cnt[i] = 0;
    if (i < NB*OUTD)  out[i] = 0.f;
}

__global__ void degree_kernel(const int* __restrict__ dst, int e) {
    int i = blockIdx.x * blockDim.x + threadIdx.x;
    if (i < e) atomicAdd(&g_deg[dst[i]], 1);
}

__global__ void dinv_kernel(int n) {
    int i = blockIdx.x * blockDim.x + threadIdx.x;
    if (i < n) g_dinv[i] = rsqrtf((float)(g_deg[i] + 1));   // +1 self loop
}

// single-block exclusive scan of deg -> rowptr, cursor
__global__ void scan_kernel(int n) {
    __shared__ int sdata[1024];
    __shared__ int carry;
    int tid = threadIdx.x;
    if (tid == 0) carry = 0;
    __syncthreads();
    for (int base = 0; base < n; base += 1024) {
        int c = carry;
        int i = base + tid;
        int v = (i < n) ? g_deg[i] : 0;
        sdata[tid] = v;
        __syncthreads();
        #pragma unroll
        for (int off = 1; off < 1024; off <<= 1) {
            int t = (tid >= off) ? sdata[tid - off] : 0;
            __syncthreads();
            sdata[tid] += t;
            __syncthreads();
        }
        int excl = c + sdata[tid] - v;
        if (i < n) { g_rowptr[i] = excl; g_cursor[i] = excl; }
        if (tid == 0) carry = c + sdata[1023];
        __syncthreads();
    }
    if (tid == 0) g_rowptr[n] = carry;
}

__global__ void csr_fill_kernel(const int* __restrict__ src,
                                const int* __restrict__ dst, int e) {
    int i = blockIdx.x * blockDim.x + threadIdx.x;
    if (i >= e) return;
    int s = src[i], d = dst[i];
    int pos = atomicAdd(&g_cursor[d], 1);
    g_csr_src[pos]  = s;
    g_csr_norm[pos] = g_dinv[s] * g_dinv[d];
}

// ---------------------------------------------------------------------------
// C[n,FO] = A[n,FI] @ W[FI,FO] (+ bias). 64x64 tile, 256 thr, 4x4 micro-tile.
template<int FI, int FO>
__global__ void gemm_kernel(const float* __restrict__ A, const float* __restrict__ W,
                            const float* __restrict__ bias, float* __restrict__ C, int n) {
    constexpr int BM = 64, BN = 64, BK = 16;
    __shared__ float As[BK][BM];
    __shared__ float Ws[BK][BN];
    int tid = threadIdx.x;
    int tn = tid & 15, tm = tid >> 4;   // 16 x 16 thread grid
    int row0 = blockIdx.x * BM;
    int col0 = blockIdx.y * BN;
    float acc[4][4] = {};
    for (int k0 = 0; k0 < FI; k0 += BK) {
        #pragma unroll
        for (int l = tid; l < BM * BK; l += 256) {
            int m = l >> 4, k = l & 15;
            int r = row0 + m, kk = k0 + k;
            As[k][m] = (r < n && kk < FI) ? A[(size_t)r * FI + kk] : 0.f;
        }
        #pragma unroll
        for (int l = tid; l < BK * BN; l += 256) {
            int k = l >> 6, cc = l & 63;
            int kk = k0 + k;
            Ws[k][cc] = (kk < FI) ? W[(size_t)kk * FO + col0 + cc] : 0.f;
        }
        __syncthreads();
        #pragma unroll
        for (int kk = 0; kk < BK; kk++) {
            float a[4], b[4];
            #pragma unroll
            for (int i = 0; i < 4; i++) a[i] = As[kk][tm * 4 + i];
            #pragma unroll
            for (int j = 0; j < 4; j++) b[j] = Ws[kk][tn * 4 + j];
            #pragma unroll
            for (int i = 0; i < 4; i++)
                #pragma unroll
                for (int j = 0; j < 4; j++)
                    acc[i][j] += a[i] * b[j];
        }
        __syncthreads();
    }
    #pragma unroll
    for (int i = 0; i < 4; i++) {
        int r = row0 + tm * 4 + i;
        if (r >= n) continue;
        #pragma unroll
        for (int j = 0; j < 4; j++) {
            int cc = col0 + tn * 4 + j;
            float v = acc[i][j];
            if (bias) v += bias[cc];
            C[(size_t)r * FO + cc] = v;
        }
    }
}

// ---------------------------------------------------------------------------
// Warp-per-node CSR aggregation: out[i] = sum_{e in N(i)} h[src_e]*norm_e + h[i]*dinv_i^2
template<int F>
__global__ void aggregate_kernel(const float* __restrict__ h, float* __restrict__ out, int n) {
    constexpr int V = F / 128;   // float4s per lane
    int wid = threadIdx.x >> 5, lane = threadIdx.x & 31;
    int node = blockIdx.x * 8 + wid;
    if (node >= n) return;
    float dself = g_dinv[node];
    float wl = dself * dself;
    float4 acc[V];
    const float4* hrow = (const float4*)(h + (size_t)node * F);
    #pragma unroll
    for (int v = 0; v < V; v++) {
        float4 t = hrow[lane + 32 * v];
        acc[v] = make_float4(t.x * wl, t.y * wl, t.z * wl, t.w * wl);
    }
    int start = g_rowptr[node], end = g_rowptr[node + 1];
    for (int e0 = start; e0 < end; e0 += 32) {
        int e = e0 + lane;
        int s = 0; float w = 0.f;
        if (e < end) { s = g_csr_src[e]; w = g_csr_norm[e]; }
        int cnt = min(32, end - e0);
        for (int j = 0; j < cnt; j++) {
            int   ss = __shfl_sync(0xffffffffu, s, j);
            float ww = __shfl_sync(0xffffffffu, w, j);
            const float4* r = (const float4*)(h + (size_t)ss * F);
            #pragma unroll
            for (int v = 0; v < V; v++) {
                float4 t = r[lane + 32 * v];
                acc[v].x += t.x * ww; acc[v].y += t.y * ww;
                acc[v].z += t.z * ww; acc[v].w += t.w * ww;
            }
        }
    }
    float4* o = (float4*)(out + (size_t)node * F);
    #pragma unroll
    for (int v = 0; v < V; v++) o[lane + 32 * v] = acc[v];
}

// ---------------------------------------------------------------------------
// out = relu(LN(agg + bias + resid) * g + b), row width 128, warp per row
__global__ void ln_kernel(const float* __restrict__ agg, const float* __restrict__ resid,
                          const float* __restrict__ bias, const float* __restrict__ gam,
                          const float* __restrict__ bet, float* __restrict__ out, int n) {
    int wid = threadIdx.x >> 5, lane = threadIdx.x & 31;
    int row = blockIdx.x * 8 + wid;
    if (row >= n) return;
    float4 v  = ((const float4*)(agg   + (size_t)row * HID))[lane];
    float4 rr = ((const float4*)(resid + (size_t)row * HID))[lane];
    float4 b4 = ((const float4*)bias)[lane];
    v.x += rr.x + b4.x; v.y += rr.y + b4.y; v.z += rr.z + b4.z; v.w += rr.w + b4.w;
    float s  = v.x + v.y + v.z + v.w;
    float sq = v.x*v.x + v.y*v.y + v.z*v.z + v.w*v.w;
    #pragma unroll
    for (int off = 16; off > 0; off >>= 1) {
        s  += __shfl_xor_sync(0xffffffffu, s,  off);
        sq += __shfl_xor_sync(0xffffffffu, sq, off);
    }
    float mu  = s * (1.f / HID);
    float var = sq * (1.f / HID) - mu * mu;
    float rs  = rsqrtf(var + 1e-5f);
    float4 g4 = ((const float4*)gam)[lane];
    float4 l4 = ((const float4*)bet)[lane];
    float4 o;
    o.x = fmaxf(0.f, (v.x - mu) * rs * g4.x + l4.x);
    o.y = fmaxf(0.f, (v.y - mu) * rs * g4.y + l4.y);
    o.z = fmaxf(0.f, (v.z - mu) * rs * g4.z + l4.z);
    o.w = fmaxf(0.f, (v.w - mu) * rs * g4.w + l4.w);
    ((float4*)(out + (size_t)row * HID))[lane] = o;
}

// ---------------------------------------------------------------------------
__global__ void cnt_kernel(const int* __restrict__ batch, int n) {
    int i = blockIdx.x * blockDim.x + threadIdx.x;
    if (i < n) atomicAdd(&g_cnt[batch[i]], 1);
}

// segment-aware pooling: block = 128 rows x 256 features; batch is sorted
__global__ void pool_kernel(const float* __restrict__ h, const int* __restrict__ batch,
                            float* __restrict__ out, int n) {
    __shared__ int sb[128];
    int r0 = blockIdx.x * 128;
    int r1 = min(n, r0 + 128);
    for (int i = threadIdx.x; i < r1 - r0; i += 256) sb[i] = batch[r0 + i];
    __syncthreads();
    int f = threadIdx.x;
    int cur = sb[0];
    float acc = 0.f;
    for (int r = r0; r < r1; r++) {
        int g = sb[r - r0];
        float val = h[(size_t)r * OUTD + f];
        if (g != cur) { atomicAdd(&out[cur * OUTD + f], acc); acc = 0.f; cur = g; }
        acc += val;
    }
    atomicAdd(&out[cur * OUTD + f], acc);
}

__global__ void final_kernel(float* out, const float* __restrict__ b3) {
    int idx = blockIdx.x * blockDim.x + threadIdx.x;
    if (idx >= NB * OUTD) return;
    int g = idx >> 8, f = idx & 255;
    float c = (float)g_cnt[g];
    out[idx] = (c > 0.f) ? (out[idx] / c + b3[f]) : 0.f;
}

// ---------------------------------------------------------------------------
extern "C" void kernel_launch(void* const* d_in, const int* in_sizes, int n_in,
                              void* d_out, int out_size) {
    const float* x     = (const float*)d_in[0];
    const int*   ei    = (const int*)d_in[1];      // int32 (JAX x64 disabled)
    const int*   batch = (const int*)d_in[2];      // int32
    const float *W1 = (const float*)d_in[3],  *b1 = (const float*)d_in[4];
    const float *W2 = (const float*)d_in[5],  *b2 = (const float*)d_in[6];
    const float *W3 = (const float*)d_in[7],  *b3 = (const float*)d_in[8];
    const float *rW = (const float*)d_in[9],  *rb = (const float*)d_in[10];
    const float *g1 = (const float*)d_in[11], *be1 = (const float*)d_in[12];
    const float *g2 = (const float*)d_in[13], *be2 = (const float*)d_in[14];
    float* out = (float*)d_out;

    int n = in_sizes[0] / 20;
    int e = in_sizes[1] / 2;
    const int* src = ei;
    const int* dst = ei + e;

    int tb = 256;
    // ---- graph preprocessing (per call; deterministic work) ----
    zero_kernel<<<(n + tb - 1) / tb, tb>>>(n, out);
    degree_kernel<<<(e + tb - 1) / tb, tb>>>(dst, e);
    dinv_kernel<<<(n + tb - 1) / tb, tb>>>(n);
    scan_kernel<<<1, 1024>>>(n);
    csr_fill_kernel<<<(e + tb - 1) / tb, tb>>>(src, dst, e);

    dim3 gemm_grid2((n + 63) / 64, 2);
    dim3 gemm_grid4((n + 63) / 64, 4);
    int agg_grid = (n + 7) / 8;

    // ---- layer 1 ----
    gemm_kernel<20, 128><<<gemm_grid2, 256>>>(x, rW, rb, g_res, n);        // residual
    gemm_kernel<20, 128><<<gemm_grid2, 256>>>(x, W1, nullptr, g_bufA, n);
    aggregate_kernel<128><<<agg_grid, 256>>>(g_bufA, g_bufB, n);
    ln_kernel<<<agg_grid, 256>>>(g_bufB, g_res, b1, g1, be1, g_hbuf, n);

    // ---- layer 2 ----
    gemm_kernel<128, 128><<<gemm_grid2, 256>>>(g_hbuf, W2, nullptr, g_bufA, n);
    aggregate_kernel<128><<<agg_grid, 256>>>(g_bufA, g_bufB, n);
    ln_kernel<<<agg_grid, 256>>>(g_bufB, g_hbuf, b2, g2, be2, g_res, n);   // g_res = h after LN2

    // ---- layer 3 ----
    gemm_kernel<128, 256><<<gemm_grid4, 256>>>(g_res, W3, nullptr, g_p256a, n);
    aggregate_kernel<256><<<agg_grid, 256>>>(g_p256a, g_p256b, n);

    // ---- pooling ----
    cnt_kernel<<<(n + tb - 1) / tb, tb>>>(batch, n);
    pool_kernel<<<(n + 127) / 128, 256>>>(g_p256b, batch, out, n);
    final_kernel<<<(NB * OUTD + tb - 1) / tb, tb>>>(out, b3);
}

// round 4
// speedup vs baseline: 1.2690x; 1.2690x over previous
#include <cuda_runtime.h>
#include <cuda_bf16.h>

// ---------------------------------------------------------------------------
// BaseGNN: 3-layer GCN, N=100000, E=1.6M, B=64.
// R3: 25.9ms pass. R4 changes: fuse LN into aggregation epilogue, fuse the two
// FI=20 GEMMs, x4-unrolled gather (MLP), warp-shuffle scan (+dinv folded),
// degree+cnt fused, packed int2 edge records. 17 launches -> 12.
// ---------------------------------------------------------------------------

#define N_MAX 100000
#define E_MAX 1600000
#define NB    64
#define HID   128
#define OUTD  256

__device__ int   g_deg[N_MAX];
__device__ int   g_rowptr[N_MAX + 1];
__device__ int   g_cursor[N_MAX];
__device__ int2  g_edge[E_MAX];          // {src, float-bits(norm)}
__device__ float g_dinv[N_MAX];
__device__ float g_bufA[(size_t)N_MAX * HID];
__device__ float g_res [(size_t)N_MAX * HID];
__device__ float g_hbuf[(size_t)N_MAX * HID];
__device__ float g_p256a[(size_t)N_MAX * OUTD];
__device__ float g_p256b[(size_t)N_MAX * OUTD];
__device__ int   g_cnt[NB];

// ---------------------------------------------------------------------------
__global__ void zero_kernel(int n, float* out) {
    int i = blockIdx.x * blockDim.x + threadIdx.x;
    if (i < n)        g_deg[i] = 0;
    if (i < NB)       g_cnt[i] = 0;
    if (i < NB*OUTD)  out[i] = 0.f;
}

// degree histogram + per-graph node counts in one pass
__global__ void hist_kernel(const int* __restrict__ dst, int e,
                            const int* __restrict__ batch, int n) {
    int i = blockIdx.x * blockDim.x + threadIdx.x;
    if (i < e) atomicAdd(&g_deg[dst[i]], 1);
    if (i < n) atomicAdd(&g_cnt[batch[i]], 1);
}

// single-block warp-shuffle exclusive scan of deg -> rowptr/cursor; also dinv
__global__ void scan_kernel(int n) {
    __shared__ int wsum[32];
    __shared__ int s_carry;
    int tid = threadIdx.x, lane = tid & 31, wid = tid >> 5;
    if (tid == 0) s_carry = 0;
    __syncthreads();
    for (int base = 0; base < n; base += 1024) {
        int i = base + tid;
        int v = (i < n) ? g_deg[i] : 0;
        if (i < n) g_dinv[i] = rsqrtf((float)(v + 1));   // +1 self loop
        int x = v;
        #pragma unroll
        for (int off = 1; off < 32; off <<= 1) {
            int t = __shfl_up_sync(0xffffffffu, x, off);
            if (lane >= off) x += t;
        }
        if (lane == 31) wsum[wid] = x;
        __syncthreads();
        if (wid == 0) {
            int s = wsum[lane];
            #pragma unroll
            for (int off = 1; off < 32; off <<= 1) {
                int t = __shfl_up_sync(0xffffffffu, s, off);
                if (lane >= off) s += t;
            }
            wsum[lane] = s;
        }
        __syncthreads();
        int carry = s_carry;
        int excl = carry + (wid ? wsum[wid - 1] : 0) + x - v;
        if (i < n) { g_rowptr[i] = excl; g_cursor[i] = excl; }
        int total = wsum[31];
        __syncthreads();
        if (tid == 0) s_carry = carry + total;
        __syncthreads();
    }
    if (tid == 0) g_rowptr[n] = s_carry;
}

__global__ void csr_fill_kernel(const int* __restrict__ src,
                                const int* __restrict__ dst, int e) {
    int i = blockIdx.x * blockDim.x + threadIdx.x;
    if (i >= e) return;
    int s = src[i], d = dst[i];
    int pos = atomicAdd(&g_cursor[d], 1);
    g_edge[pos] = make_int2(s, __float_as_int(g_dinv[s] * g_dinv[d]));
}

// ---------------------------------------------------------------------------
// Fused input GEMMs: outA = x@W1 ; outR = x@res_W + res_b. Warp per row.
__global__ void gemm_in_kernel(const float* __restrict__ x, const float* __restrict__ W1,
                               const float* __restrict__ rW, const float* __restrict__ rb,
                               float* __restrict__ outA, float* __restrict__ outR, int n) {
    __shared__ float sW1[20 * 128];
    __shared__ float sRW[20 * 128];
    __shared__ float sRB[128];
    int tid = threadIdx.x;
    for (int i = tid; i < 20 * 128; i += 256) { sW1[i] = W1[i]; sRW[i] = rW[i]; }
    if (tid < 128) sRB[tid] = rb[tid];
    __syncthreads();
    int lane = tid & 31, wid = tid >> 5;
    int row = blockIdx.x * 8 + wid;
    if (row >= n) return;
    float xv = (lane < 20) ? x[(size_t)row * 20 + lane] : 0.f;
    float4 a = make_float4(0.f, 0.f, 0.f, 0.f);
    float4 r = make_float4(0.f, 0.f, 0.f, 0.f);
    #pragma unroll
    for (int k = 0; k < 20; k++) {
        float xk = __shfl_sync(0xffffffffu, xv, k);
        float4 w = ((const float4*)(sW1 + k * 128))[lane];
        a.x += xk * w.x; a.y += xk * w.y; a.z += xk * w.z; a.w += xk * w.w;
        float4 v = ((const float4*)(sRW + k * 128))[lane];
        r.x += xk * v.x; r.y += xk * v.y; r.z += xk * v.z; r.w += xk * v.w;
    }
    float4 rb4 = ((const float4*)sRB)[lane];
    r.x += rb4.x; r.y += rb4.y; r.z += rb4.z; r.w += rb4.w;
    ((float4*)(outA + (size_t)row * HID))[lane] = a;
    ((float4*)(outR + (size_t)row * HID))[lane] = r;
}

// ---------------------------------------------------------------------------
// C[n,FO] = A[n,FI] @ W[FI,FO]. 64x64 tile, 256 thr, 4x4 micro-tile.
template<int FI, int FO>
__global__ void gemm_kernel(const float* __restrict__ A, const float* __restrict__ W,
                            float* __restrict__ C, int n) {
    constexpr int BM = 64, BN = 64, BK = 16;
    __shared__ float As[BK][BM];
    __shared__ float Ws[BK][BN];
    int tid = threadIdx.x;
    int tn = tid & 15, tm = tid >> 4;
    int row0 = blockIdx.x * BM;
    int col0 = blockIdx.y * BN;
    float acc[4][4] = {};
    for (int k0 = 0; k0 < FI; k0 += BK) {
        #pragma unroll
        for (int l = tid; l < BM * BK; l += 256) {
            int m = l >> 4, k = l & 15;
            int r = row0 + m, kk = k0 + k;
            As[k][m] = (r < n) ? A[(size_t)r * FI + kk] : 0.f;
        }
        #pragma unroll
        for (int l = tid; l < BK * BN; l += 256) {
            int k = l >> 6, cc = l & 63;
            Ws[k][cc] = W[(size_t)(k0 + k) * FO + col0 + cc];
        }
        __syncthreads();
        #pragma unroll
        for (int kk = 0; kk < BK; kk++) {
            float a[4], b[4];
            #pragma unroll
            for (int i = 0; i < 4; i++) a[i] = As[kk][tm * 4 + i];
            #pragma unroll
            for (int j = 0; j < 4; j++) b[j] = Ws[kk][tn * 4 + j];
            #pragma unroll
            for (int i = 0; i < 4; i++)
                #pragma unroll
                for (int j = 0; j < 4; j++)
                    acc[i][j] += a[i] * b[j];
        }
        __syncthreads();
    }
    #pragma unroll
    for (int i = 0; i < 4; i++) {
        int r = row0 + tm * 4 + i;
        if (r >= n) continue;
        #pragma unroll
        for (int j = 0; j < 4; j++)
            C[(size_t)r * FO + col0 + tn * 4 + j] = acc[i][j];
    }
}

// ---------------------------------------------------------------------------
// Fused aggregate + bias + residual + LN + ReLU (F=128). Warp per node.
__global__ void agg_ln_kernel(const float* __restrict__ h, const float* __restrict__ resid,
                              const float* __restrict__ bias, const float* __restrict__ gam,
                              const float* __restrict__ bet, float* __restrict__ out, int n) {
    int wid = threadIdx.x >> 5, lane = threadIdx.x & 31;
    int node = blockIdx.x * 8 + wid;
    if (node >= n) return;
    float dself = g_dinv[node];
    float wl = dself * dself;
    float4 t = ((const float4*)(h + (size_t)node * HID))[lane];
    float4 acc = make_float4(t.x * wl, t.y * wl, t.z * wl, t.w * wl);
    int start = g_rowptr[node], end = g_rowptr[node + 1];
    for (int e0 = start; e0 < end; e0 += 32) {
        int e = e0 + lane;
        int2 rec = (e < end) ? g_edge[e] : make_int2(0, 0);
        int cnt = min(32, end - e0);
        int j = 0;
        for (; j + 4 <= cnt; j += 4) {
            int   s0 = __shfl_sync(0xffffffffu, rec.x, j);
            int   s1 = __shfl_sync(0xffffffffu, rec.x, j + 1);
            int   s2 = __shfl_sync(0xffffffffu, rec.x, j + 2);
            int   s3 = __shfl_sync(0xffffffffu, rec.x, j + 3);
            float w0 = __int_as_float(__shfl_sync(0xffffffffu, rec.y, j));
            float w1 = __int_as_float(__shfl_sync(0xffffffffu, rec.y, j + 1));
            float w2 = __int_as_float(__shfl_sync(0xffffffffu, rec.y, j + 2));
            float w3 = __int_as_float(__shfl_sync(0xffffffffu, rec.y, j + 3));
            float4 a0 = ((const float4*)(h + (size_t)s0 * HID))[lane];
            float4 a1 = ((const float4*)(h + (size_t)s1 * HID))[lane];
            float4 a2 = ((const float4*)(h + (size_t)s2 * HID))[lane];
            float4 a3 = ((const float4*)(h + (size_t)s3 * HID))[lane];
            acc.x += a0.x * w0 + a1.x * w1 + a2.x * w2 + a3.x * w3;
            acc.y += a0.y * w0 + a1.y * w1 + a2.y * w2 + a3.y * w3;
            acc.z += a0.z * w0 + a1.z * w1 + a2.z * w2 + a3.z * w3;
            acc.w += a0.w * w0 + a1.w * w1 + a2.w * w2 + a3.w * w3;
        }
        for (; j < cnt; j++) {
            int   ss = __shfl_sync(0xffffffffu, rec.x, j);
            float ww = __int_as_float(__shfl_sync(0xffffffffu, rec.y, j));
            float4 a0 = ((const float4*)(h + (size_t)ss * HID))[lane];
            acc.x += a0.x * ww; acc.y += a0.y * ww;
            acc.z += a0.z * ww; acc.w += a0.w * ww;
        }
    }
    // epilogue: + bias + residual, LN, ReLU
    float4 rr = ((const float4*)(resid + (size_t)node * HID))[lane];
    float4 b4 = ((const float4*)bias)[lane];
    acc.x += rr.x + b4.x; acc.y += rr.y + b4.y;
    acc.z += rr.z + b4.z; acc.w += rr.w + b4.w;
    float s  = acc.x + acc.y + acc.z + acc.w;
    float sq = acc.x*acc.x + acc.y*acc.y + acc.z*acc.z + acc.w*acc.w;
    #pragma unroll
    for (int off = 16; off > 0; off >>= 1) {
        s  += __shfl_xor_sync(0xffffffffu, s,  off);
        sq += __shfl_xor_sync(0xffffffffu, sq, off);
    }
    float mu  = s * (1.f / HID);
    float var = sq * (1.f / HID) - mu * mu;
    float rs  = rsqrtf(var + 1e-5f);
    float4 g4 = ((const float4*)gam)[lane];
    float4 l4 = ((const float4*)bet)[lane];
    float4 o;
    o.x = fmaxf(0.f, (acc.x - mu) * rs * g4.x + l4.x);
    o.y = fmaxf(0.f, (acc.y - mu) * rs * g4.y + l4.y);
    o.z = fmaxf(0.f, (acc.z - mu) * rs * g4.z + l4.z);
    o.w = fmaxf(0.f, (acc.w - mu) * rs * g4.w + l4.w);
    ((float4*)(out + (size_t)node * HID))[lane] = o;
}

// Aggregation only, F=256 (2 float4 per lane), x4 MLP unroll.
__global__ void agg256_kernel(const float* __restrict__ h, float* __restrict__ out, int n) {
    int wid = threadIdx.x >> 5, lane = threadIdx.x & 31;
    int node = blockIdx.x * 8 + wid;
    if (node >= n) return;
    float dself = g_dinv[node];
    float wl = dself * dself;
    const float4* hrow = (const float4*)(h + (size_t)node * OUTD);
    float4 acc0 = hrow[lane], acc1 = hrow[lane + 32];
    acc0.x *= wl; acc0.y *= wl; acc0.z *= wl; acc0.w *= wl;
    acc1.x *= wl; acc1.y *= wl; acc1.z *= wl; acc1.w *= wl;
    int start = g_rowptr[node], end = g_rowptr[node + 1];
    for (int e0 = start; e0 < end; e0 += 32) {
        int e = e0 + lane;
        int2 rec = (e < end) ? g_edge[e] : make_int2(0, 0);
        int cnt = min(32, end - e0);
        int j = 0;
        for (; j + 2 <= cnt; j += 2) {
            int   s0 = __shfl_sync(0xffffffffu, rec.x, j);
            int   s1 = __shfl_sync(0xffffffffu, rec.x, j + 1);
            float w0 = __int_as_float(__shfl_sync(0xffffffffu, rec.y, j));
            float w1 = __int_as_float(__shfl_sync(0xffffffffu, rec.y, j + 1));
            const float4* r0 = (const float4*)(h + (size_t)s0 * OUTD);
            const float4* r1 = (const float4*)(h + (size_t)s1 * OUTD);
            float4 a0 = r0[lane], b0 = r0[lane + 32];
            float4 a1 = r1[lane], b1 = r1[lane + 32];
            acc0.x += a0.x * w0 + a1.x * w1; acc0.y += a0.y * w0 + a1.y * w1;
            acc0.z += a0.z * w0 + a1.z * w1; acc0.w += a0.w * w0 + a1.w * w1;
            acc1.x += b0.x * w0 + b1.x * w1; acc1.y += b0.y * w0 + b1.y * w1;
            acc1.z += b0.z * w0 + b1.z * w1; acc1.w += b0.w * w0 + b1.w * w1;
        }
        for (; j < cnt; j++) {
            int   ss = __shfl_sync(0xffffffffu, rec.x, j);
            float ww = __int_as_float(__shfl_sync(0xffffffffu, rec.y, j));
            const float4* r0 = (const float4*)(h + (size_t)ss * OUTD);
            float4 a0 = r0[lane], b0 = r0[lane + 32];
            acc0.x += a0.x * ww; acc0.y += a0.y * ww; acc0.z += a0.z * ww; acc0.w += a0.w * ww;
            acc1.x += b0.x * ww; acc1.y += b0.y * ww; acc1.z += b0.z * ww; acc1.w += b0.w * ww;
        }
    }
    float4* o = (float4*)(out + (size_t)node * OUTD);
    o[lane] = acc0; o[lane + 32] = acc1;
}

// ---------------------------------------------------------------------------
// segment-aware pooling: block = 128 rows x 256 features; batch is sorted
__global__ void pool_kernel(const float* __restrict__ h, const int* __restrict__ batch,
                            float* __restrict__ out, int n) {
    __shared__ int sb[128];
    int r0 = blockIdx.x * 128;
    int r1 = min(n, r0 + 128);
    for (int i = threadIdx.x; i < r1 - r0; i += 256) sb[i] = batch[r0 + i];
    __syncthreads();
    int f = threadIdx.x;
    int cur = sb[0];
    float acc = 0.f;
    for (int r = r0; r < r1; r++) {
        int g = sb[r - r0];
        float val = h[(size_t)r * OUTD + f];
        if (g != cur) { atomicAdd(&out[cur * OUTD + f], acc); acc = 0.f; cur = g; }
        acc += val;
    }
    atomicAdd(&out[cur * OUTD + f], acc);
}

__global__ void final_kernel(float* out, const float* __restrict__ b3) {
    int idx = blockIdx.x * blockDim.x + threadIdx.x;
    if (idx >= NB * OUTD) return;
    int g = idx >> 8, f = idx & 255;
    float c = (float)g_cnt[g];
    out[idx] = (c > 0.f) ? (out[idx] / c + b3[f]) : 0.f;
}

// ---------------------------------------------------------------------------
extern "C" void kernel_launch(void* const* d_in, const int* in_sizes, int n_in,
                              void* d_out, int out_size) {
    const float* x     = (const float*)d_in[0];
    const int*   ei    = (const int*)d_in[1];      // int32 (JAX x64 disabled)
    const int*   batch = (const int*)d_in[2];
    const float *W1 = (const float*)d_in[3],  *b1 = (const float*)d_in[4];
    const float *W2 = (const float*)d_in[5],  *b2 = (const float*)d_in[6];
    const float *W3 = (const float*)d_in[7],  *b3 = (const float*)d_in[8];
    const float *rW = (const float*)d_in[9],  *rb = (const float*)d_in[10];
    const float *g1 = (const float*)d_in[11], *be1 = (const float*)d_in[12];
    const float *g2 = (const float*)d_in[13], *be2 = (const float*)d_in[14];
    float* out = (float*)d_out;

    int n = in_sizes[0] / 20;
    int e = in_sizes[1] / 2;
    const int* src = ei;
    const int* dst = ei + e;

    int tb = 256;
    int wgrid = (n + 7) / 8;   // warp-per-row grids

    // ---- graph preprocessing ----
    zero_kernel<<<(n + tb - 1) / tb, tb>>>(n, out);
    hist_kernel<<<(e + tb - 1) / tb, tb>>>(dst, e, batch, n);
    scan_kernel<<<1, 1024>>>(n);
    csr_fill_kernel<<<(e + tb - 1) / tb, tb>>>(src, dst, e);

    dim3 gemm_grid2((n + 63) / 64, 2);
    dim3 gemm_grid4((n + 63) / 64, 4);

    // ---- layer 1 ----
    gemm_in_kernel<<<wgrid, 256>>>(x, W1, rW, rb, g_bufA, g_res, n);
    agg_ln_kernel<<<wgrid, 256>>>(g_bufA, g_res, b1, g1, be1, g_hbuf, n);

    // ---- layer 2 ----
    gemm_kernel<128, 128><<<gemm_grid2, 256>>>(g_hbuf, W2, g_bufA, n);
    agg_ln_kernel<<<wgrid, 256>>>(g_bufA, g_hbuf, b2, g2, be2, g_res, n);

    // ---- layer 3 ----
    gemm_kernel<128, 256><<<gemm_grid4, 256>>>(g_res, W3, g_p256a, n);
    agg256_kernel<<<wgrid, 256>>>(g_p256a, g_p256b, n);

    // ---- pooling ----
    pool_kernel<<<(n + 127) / 128, 256>>>(g_p256b, batch, out, n);
    final_kernel<<<(NB * OUTD + tb - 1) / tb, tb>>>(out, b3);
}

// round 5
// speedup vs baseline: 15.1814x; 11.9636x over previous
#include <cuda_runtime.h>
#include <cuda_bf16.h>

// ---------------------------------------------------------------------------
// BaseGNN: 3-layer GCN, N=100000, E=1.6M, B=64.
// R5: ONE persistent kernel with software grid barriers (theory: ~1.6ms/launch
// overhead dominated R3/R4). 444 blocks x 256 thr, __launch_bounds__(256,3)
// guarantees co-residency on 148+ SMs. Even barrier count -> barrier state
// self-resets across CUDA-graph replays. Block 0 scans while others GEMM.
// ---------------------------------------------------------------------------

#define N_MAX 100000
#define E_MAX 1600000
#define NB    64
#define HID   128
#define OUTD  256
#define NBLK  444
#define NTHR  256
#define NWARP (NBLK * 8)

__device__ int   g_deg[N_MAX];
__device__ int   g_rowptr[N_MAX + 1];
__device__ int   g_cursor[N_MAX];
__device__ int2  g_edge[E_MAX];          // {src, float-bits(norm)}
__device__ float g_bufA[(size_t)N_MAX * HID];
__device__ float g_res [(size_t)N_MAX * HID];
__device__ float g_hbuf[(size_t)N_MAX * HID];
__device__ float g_p256a[(size_t)N_MAX * OUTD];
__device__ float g_p256b[(size_t)N_MAX * OUTD];
__device__ int   g_cnt[NB];
__device__ unsigned g_bar_count = 0;
__device__ unsigned g_bar_sense = 0;

// sense-reversing software grid barrier (all NBLK blocks co-resident).
// Even number of calls per kernel -> g_bar_sense returns to 0 for next replay.
__device__ __forceinline__ void grid_barrier(unsigned& ls) {
    __threadfence();
    __syncthreads();
    ls ^= 1u;
    if (threadIdx.x == 0) {
        unsigned arrived = atomicAdd(&g_bar_count, 1u);
        if (arrived == NBLK - 1u) {
            atomicExch(&g_bar_count, 0u);
            __threadfence();
            atomicExch(&g_bar_sense, ls);
        } else {
            while (((volatile unsigned*)&g_bar_sense)[0] != ls) __nanosleep(64);
            __threadfence();
        }
    }
    __syncthreads();
}

// ---------------------------------------------------------------------------
// GEMM phase: C[n,FO] = A[n,128] @ W[128,FO]; 64x64 tiles, block-strided tiles.
template<int FO>
__device__ void gemm_phase(const float* __restrict__ A, const float* __restrict__ W,
                           float* __restrict__ C, int n, float* sh) {
    const int rowTiles = (n + 63) >> 6;
    const int ntiles = rowTiles * (FO >> 6);
    float (*As)[68] = (float(*)[68])sh;              // [16][68]
    float (*Ws)[64] = (float(*)[64])(sh + 16 * 68);  // [16][64]
    int tid = threadIdx.x;
    int tn = tid & 15, tm = tid >> 4;
    for (int t = blockIdx.x; t < ntiles; t += NBLK) {
        int row0 = (t % rowTiles) << 6;
        int col0 = (t / rowTiles) << 6;
        float acc[4][4] = {};
        for (int k0 = 0; k0 < 128; k0 += 16) {
            #pragma unroll
            for (int l = tid; l < 64 * 16; l += NTHR) {
                int m = l >> 4, k = l & 15;
                int r = row0 + m;
                As[k][m] = (r < n) ? A[(size_t)r * 128 + k0 + k] : 0.f;
            }
            #pragma unroll
            for (int l = tid; l < 16 * 64; l += NTHR) {
                int k = l >> 6, c = l & 63;
                Ws[k][c] = W[(size_t)(k0 + k) * FO + col0 + c];
            }
            __syncthreads();
            #pragma unroll
            for (int kk = 0; kk < 16; kk++) {
                float a[4], b[4];
                #pragma unroll
                for (int i = 0; i < 4; i++) a[i] = As[kk][tm * 4 + i];
                #pragma unroll
                for (int j = 0; j < 4; j++) b[j] = Ws[kk][tn * 4 + j];
                #pragma unroll
                for (int i = 0; i < 4; i++)
                    #pragma unroll
                    for (int j = 0; j < 4; j++)
                        acc[i][j] += a[i] * b[j];
            }
            __syncthreads();
        }
        #pragma unroll
        for (int i = 0; i < 4; i++) {
            int r = row0 + tm * 4 + i;
            if (r >= n) continue;
            #pragma unroll
            for (int j = 0; j < 4; j++)
                C[(size_t)r * FO + col0 + tn * 4 + j] = acc[i][j];
        }
    }
}

// ---------------------------------------------------------------------------
// Fused aggregate + bias + residual + LN + ReLU (F=128), warp-per-node.
__device__ void agg_ln_phase(const float* __restrict__ h, const float* __restrict__ resid,
                             const float* __restrict__ bias, const float* __restrict__ gam,
                             const float* __restrict__ bet, float* __restrict__ outp,
                             int n, int gwarp, int lane) {
    for (int node = gwarp; node < n; node += NWARP) {
        float wl = 1.f / (float)(g_deg[node] + 1);
        float4 t = ((const float4*)(h + (size_t)node * HID))[lane];
        float4 acc = make_float4(t.x * wl, t.y * wl, t.z * wl, t.w * wl);
        int start = g_rowptr[node], end = g_rowptr[node + 1];
        for (int e0 = start; e0 < end; e0 += 32) {
            int e = e0 + lane;
            int2 rec = (e < end) ? g_edge[e] : make_int2(0, 0);
            int cnt = min(32, end - e0);
            int j = 0;
            for (; j + 4 <= cnt; j += 4) {
                int   s0 = __shfl_sync(0xffffffffu, rec.x, j);
                int   s1 = __shfl_sync(0xffffffffu, rec.x, j + 1);
                int   s2 = __shfl_sync(0xffffffffu, rec.x, j + 2);
                int   s3 = __shfl_sync(0xffffffffu, rec.x, j + 3);
                float w0 = __int_as_float(__shfl_sync(0xffffffffu, rec.y, j));
                float w1 = __int_as_float(__shfl_sync(0xffffffffu, rec.y, j + 1));
                float w2 = __int_as_float(__shfl_sync(0xffffffffu, rec.y, j + 2));
                float w3 = __int_as_float(__shfl_sync(0xffffffffu, rec.y, j + 3));
                float4 a0 = ((const float4*)(h + (size_t)s0 * HID))[lane];
                float4 a1 = ((const float4*)(h + (size_t)s1 * HID))[lane];
                float4 a2 = ((const float4*)(h + (size_t)s2 * HID))[lane];
                float4 a3 = ((const float4*)(h + (size_t)s3 * HID))[lane];
                acc.x += a0.x * w0 + a1.x * w1 + a2.x * w2 + a3.x * w3;
                acc.y += a0.y * w0 + a1.y * w1 + a2.y * w2 + a3.y * w3;
                acc.z += a0.z * w0 + a1.z * w1 + a2.z * w2 + a3.z * w3;
                acc.w += a0.w * w0 + a1.w * w1 + a2.w * w2 + a3.w * w3;
            }
            for (; j < cnt; j++) {
                int   ss = __shfl_sync(0xffffffffu, rec.x, j);
                float ww = __int_as_float(__shfl_sync(0xffffffffu, rec.y, j));
                float4 a0 = ((const float4*)(h + (size_t)ss * HID))[lane];
                acc.x += a0.x * ww; acc.y += a0.y * ww;
                acc.z += a0.z * ww; acc.w += a0.w * ww;
            }
        }
        float4 rr = ((const float4*)(resid + (size_t)node * HID))[lane];
        float4 b4 = ((const float4*)bias)[lane];
        acc.x += rr.x + b4.x; acc.y += rr.y + b4.y;
        acc.z += rr.z + b4.z; acc.w += rr.w + b4.w;
        float s  = acc.x + acc.y + acc.z + acc.w;
        float sq = acc.x*acc.x + acc.y*acc.y + acc.z*acc.z + acc.w*acc.w;
        #pragma unroll
        for (int off = 16; off > 0; off >>= 1) {
            s  += __shfl_xor_sync(0xffffffffu, s,  off);
            sq += __shfl_xor_sync(0xffffffffu, sq, off);
        }
        float mu  = s * (1.f / HID);
        float var = sq * (1.f / HID) - mu * mu;
        float rs  = rsqrtf(var + 1e-5f);
        float4 g4 = ((const float4*)gam)[lane];
        float4 l4 = ((const float4*)bet)[lane];
        float4 o;
        o.x = fmaxf(0.f, (acc.x - mu) * rs * g4.x + l4.x);
        o.y = fmaxf(0.f, (acc.y - mu) * rs * g4.y + l4.y);
        o.z = fmaxf(0.f, (acc.z - mu) * rs * g4.z + l4.z);
        o.w = fmaxf(0.f, (acc.w - mu) * rs * g4.w + l4.w);
        ((float4*)(outp + (size_t)node * HID))[lane] = o;
    }
}

// ---------------------------------------------------------------------------
__global__ void __launch_bounds__(NTHR, 3) mega_kernel(
    const float* __restrict__ x, const int* __restrict__ src,
    const int* __restrict__ dst, const int* __restrict__ batch,
    const float* __restrict__ W1, const float* __restrict__ b1,
    const float* __restrict__ W2, const float* __restrict__ b2,
    const float* __restrict__ W3, const float* __restrict__ b3,
    const float* __restrict__ rW, const float* __restrict__ rb,
    const float* __restrict__ g1, const float* __restrict__ be1,
    const float* __restrict__ g2, const float* __restrict__ be2,
    float* __restrict__ out, int n, int e)
{
    __shared__ float sh[5248];
    unsigned ls = 0;
    const int tid  = threadIdx.x;
    const int gtid = blockIdx.x * NTHR + tid;
    const int gstr = NBLK * NTHR;
    const int lane = tid & 31, wid = tid >> 5;
    const int gwarp = blockIdx.x * 8 + wid;

    // ---- P0: zero ----
    for (int i = gtid; i < n; i += gstr) g_deg[i] = 0;
    if (gtid < NB) g_cnt[gtid] = 0;
    for (int i = gtid; i < NB * OUTD; i += gstr) out[i] = 0.f;
    grid_barrier(ls);                                            // B1

    // ---- P1: histograms ----
    for (int i = gtid; i < e; i += gstr) atomicAdd(&g_deg[dst[i]], 1);
    for (int i = gtid; i < n; i += gstr) atomicAdd(&g_cnt[batch[i]], 1);
    grid_barrier(ls);                                            // B2

    // ---- P2: block 0 scans deg->rowptr/cursor; blocks 1..443 do input GEMMs ----
    if (blockIdx.x == 0) {
        int* wsum = (int*)sh;   // 8 entries
        int carry = 0;
        for (int base = 0; base < n; base += NTHR) {
            int i = base + tid;
            int v = (i < n) ? g_deg[i] : 0;
            int xv = v;
            #pragma unroll
            for (int off = 1; off < 32; off <<= 1) {
                int t = __shfl_up_sync(0xffffffffu, xv, off);
                if (lane >= off) xv += t;
            }
            if (lane == 31) wsum[wid] = xv;
            __syncthreads();
            if (wid == 0) {
                int sv = (lane < 8) ? wsum[lane] : 0;
                #pragma unroll
                for (int off = 1; off < 8; off <<= 1) {
                    int t = __shfl_up_sync(0xffffffffu, sv, off);
                    if (lane >= off) sv += t;
                }
                if (lane < 8) wsum[lane] = sv;
            }
            __syncthreads();
            int excl = carry + (wid ? wsum[wid - 1] : 0) + xv - v;
            if (i < n) { g_rowptr[i] = excl; g_cursor[i] = excl; }
            int total = wsum[7];
            __syncthreads();
            carry += total;
        }
        if (tid == 0) g_rowptr[n] = carry;
    } else {
        float* sW1 = sh;            // 2560
        float* sRW = sh + 2560;     // 2560
        float* sRB = sh + 5120;     // 128
        for (int i = tid; i < 20 * 128; i += NTHR) { sW1[i] = W1[i]; sRW[i] = rW[i]; }
        if (tid < 128) sRB[tid] = rb[tid];
        __syncthreads();
        int w2 = (blockIdx.x - 1) * 8 + wid;
        for (int row = w2; row < n; row += (NBLK - 1) * 8) {
            float xv = (lane < 20) ? x[(size_t)row * 20 + lane] : 0.f;
            float4 a = make_float4(0.f, 0.f, 0.f, 0.f);
            float4 r = make_float4(0.f, 0.f, 0.f, 0.f);
            #pragma unroll
            for (int k = 0; k < 20; k++) {
                float xk = __shfl_sync(0xffffffffu, xv, k);
                float4 w = ((const float4*)(sW1 + k * 128))[lane];
                a.x += xk * w.x; a.y += xk * w.y; a.z += xk * w.z; a.w += xk * w.w;
                float4 v = ((const float4*)(sRW + k * 128))[lane];
                r.x += xk * v.x; r.y += xk * v.y; r.z += xk * v.z; r.w += xk * v.w;
            }
            float4 rb4 = ((const float4*)sRB)[lane];
            r.x += rb4.x; r.y += rb4.y; r.z += rb4.z; r.w += rb4.w;
            ((float4*)(g_bufA + (size_t)row * HID))[lane] = a;
            ((float4*)(g_res  + (size_t)row * HID))[lane] = r;
        }
    }
    grid_barrier(ls);                                            // B3

    // ---- P3: csr fill (norm from degrees; deg>=0, +1 self-loop) ----
    for (int i = gtid; i < e; i += gstr) {
        int s = src[i], d = dst[i];
        int pos = atomicAdd(&g_cursor[d], 1);
        float nrm = rsqrtf((float)(g_deg[s] + 1) * (float)(g_deg[d] + 1));
        g_edge[pos] = make_int2(s, __float_as_int(nrm));
    }
    grid_barrier(ls);                                            // B4

    // ---- layer 1 aggregation + LN ----
    agg_ln_phase(g_bufA, g_res, b1, g1, be1, g_hbuf, n, gwarp, lane);
    grid_barrier(ls);                                            // B5

    // ---- layer 2 GEMM ----
    gemm_phase<128>(g_hbuf, W2, g_bufA, n, sh);
    grid_barrier(ls);                                            // B6

    agg_ln_phase(g_bufA, g_hbuf, b2, g2, be2, g_res, n, gwarp, lane);
    grid_barrier(ls);                                            // B7

    // ---- layer 3 GEMM ----
    gemm_phase<256>(g_res, W3, g_p256a, n, sh);
    grid_barrier(ls);                                            // B8

    // ---- layer 3 aggregation (F=256) ----
    for (int node = gwarp; node < n; node += NWARP) {
        float wl = 1.f / (float)(g_deg[node] + 1);
        const float4* hrow = (const float4*)(g_p256a + (size_t)node * OUTD);
        float4 acc0 = hrow[lane], acc1 = hrow[lane + 32];
        acc0.x *= wl; acc0.y *= wl; acc0.z *= wl; acc0.w *= wl;
        acc1.x *= wl; acc1.y *= wl; acc1.z *= wl; acc1.w *= wl;
        int start = g_rowptr[node], end = g_rowptr[node + 1];
        for (int e0 = start; e0 < end; e0 += 32) {
            int ee = e0 + lane;
            int2 rec = (ee < end) ? g_edge[ee] : make_int2(0, 0);
            int cnt = min(32, end - e0);
            int j = 0;
            for (; j + 2 <= cnt; j += 2) {
                int   s0 = __shfl_sync(0xffffffffu, rec.x, j);
                int   s1 = __shfl_sync(0xffffffffu, rec.x, j + 1);
                float w0 = __int_as_float(__shfl_sync(0xffffffffu, rec.y, j));
                float w1 = __int_as_float(__shfl_sync(0xffffffffu, rec.y, j + 1));
                const float4* r0 = (const float4*)(g_p256a + (size_t)s0 * OUTD);
                const float4* r1 = (const float4*)(g_p256a + (size_t)s1 * OUTD);
                float4 a0 = r0[lane], b0 = r0[lane + 32];
                float4 a1 = r1[lane], b1v = r1[lane + 32];
                acc0.x += a0.x * w0 + a1.x * w1; acc0.y += a0.y * w0 + a1.y * w1;
                acc0.z += a0.z * w0 + a1.z * w1; acc0.w += a0.w * w0 + a1.w * w1;
                acc1.x += b0.x * w0 + b1v.x * w1; acc1.y += b0.y * w0 + b1v.y * w1;
                acc1.z += b0.z * w0 + b1v.z * w1; acc1.w += b0.w * w0 + b1v.w * w1;
            }
            for (; j < cnt; j++) {
                int   ss = __shfl_sync(0xffffffffu, rec.x, j);
                float ww = __int_as_float(__shfl_sync(0xffffffffu, rec.y, j));
                const float4* r0 = (const float4*)(g_p256a + (size_t)ss * OUTD);
                float4 a0 = r0[lane], b0 = r0[lane + 32];
                acc0.x += a0.x * ww; acc0.y += a0.y * ww; acc0.z += a0.z * ww; acc0.w += a0.w * ww;
                acc1.x += b0.x * ww; acc1.y += b0.y * ww; acc1.z += b0.z * ww; acc1.w += b0.w * ww;
            }
        }
        float4* o = (float4*)(g_p256b + (size_t)node * OUTD);
        o[lane] = acc0; o[lane + 32] = acc1;
    }
    grid_barrier(ls);                                            // B9

    // ---- pooling (batch sorted; segment-aware, few atomics) ----
    {
        int* sb = (int*)sh;
        for (int c = blockIdx.x; c * 128 < n; c += NBLK) {
            int r0 = c * 128;
            int r1 = min(n, r0 + 128);
            __syncthreads();
            if (tid < r1 - r0) sb[tid] = batch[r0 + tid];
            __syncthreads();
            int f = tid;
            int cur = sb[0];
            float acc = 0.f;
            for (int r = r0; r < r1; r++) {
                int g = sb[r - r0];
                float val = g_p256b[(size_t)r * OUTD + f];
                if (g != cur) { atomicAdd(&out[cur * OUTD + f], acc); acc = 0.f; cur = g; }
                acc += val;
            }
            atomicAdd(&out[cur * OUTD + f], acc);
        }
    }
    grid_barrier(ls);                                            // B10 (even count)

    // ---- final: divide by counts, add conv3 bias ----
    for (int i = gtid; i < NB * OUTD; i += gstr) {
        int g = i >> 8, f = i & 255;
        float c = (float)g_cnt[g];
        out[i] = (c > 0.f) ? (out[i] / c + b3[f]) : 0.f;
    }
}

// ---------------------------------------------------------------------------
extern "C" void kernel_launch(void* const* d_in, const int* in_sizes, int n_in,
                              void* d_out, int out_size) {
    const float* x     = (const float*)d_in[0];
    const int*   ei    = (const int*)d_in[1];      // int32 (JAX x64 disabled)
    const int*   batch = (const int*)d_in[2];
    const float *W1 = (const float*)d_in[3],  *b1 = (const float*)d_in[4];
    const float *W2 = (const float*)d_in[5],  *b2 = (const float*)d_in[6];
    const float *W3 = (const float*)d_in[7],  *b3 = (const float*)d_in[8];
    const float *rW = (const float*)d_in[9],  *rb = (const float*)d_in[10];
    const float *g1 = (const float*)d_in[11], *be1 = (const float*)d_in[12];
    const float *g2 = (const float*)d_in[13], *be2 = (const float*)d_in[14];
    float* out = (float*)d_out;

    int n = in_sizes[0] / 20;
    int e = in_sizes[1] / 2;
    const int* src = ei;
    const int* dst = ei + e;

    mega_kernel<<<NBLK, NTHR>>>(x, src, dst, batch,
                                W1, b1, W2, b2, W3, b3, rW, rb,
                                g1, be1, g2, be2, out, n, e);
}

// round 6
// speedup vs baseline: 28.3606x; 1.8681x over previous
#include <cuda_runtime.h>
#include <cuda_bf16.h>

// ---------------------------------------------------------------------------
// BaseGNN: 3-layer GCN, N=100000, E=1.6M, B=64. Persistent mega-kernel (R5:
// 1.71ms). R6: layer-3 linearity refactor — pooled = pool(A_norm@H) @ W3 + b3,
// eliminating the N*256 GEMM (6.6 GF), the 256-wide aggregation, and all
// N*256 buffers. 10 grid barriers (even -> sense self-resets per replay).
// ---------------------------------------------------------------------------

#define N_MAX 100000
#define E_MAX 1600000
#define NB    64
#define HID   128
#define OUTD  256
#define NBLK  444
#define NTHR  256
#define NWARP (NBLK * 8)

__device__ int   g_deg[N_MAX];
__device__ int   g_rowptr[N_MAX + 1];
__device__ int   g_cursor[N_MAX];
__device__ int2  g_edge[E_MAX];          // {src, float-bits(norm)}
__device__ float g_bufA[(size_t)N_MAX * HID];
__device__ float g_res [(size_t)N_MAX * HID];
__device__ float g_hbuf[(size_t)N_MAX * HID];
__device__ float g_pool[NB * HID];
__device__ int   g_cnt[NB];
__device__ unsigned g_bar_count = 0;
__device__ unsigned g_bar_sense = 0;

// sense-reversing software grid barrier (all NBLK blocks co-resident).
// Even number of calls per kernel -> g_bar_sense returns to 0 for next replay.
__device__ __forceinline__ void grid_barrier(unsigned& ls) {
    __threadfence();
    __syncthreads();
    ls ^= 1u;
    if (threadIdx.x == 0) {
        unsigned arrived = atomicAdd(&g_bar_count, 1u);
        if (arrived == NBLK - 1u) {
            atomicExch(&g_bar_count, 0u);
            __threadfence();
            atomicExch(&g_bar_sense, ls);
        } else {
            while (((volatile unsigned*)&g_bar_sense)[0] != ls) __nanosleep(64);
            __threadfence();
        }
    }
    __syncthreads();
}

// ---------------------------------------------------------------------------
// GEMM phase: C[n,128] = A[n,128] @ W[128,128]; 64x64 tiles, block-strided.
__device__ void gemm_phase128(const float* __restrict__ A, const float* __restrict__ W,
                              float* __restrict__ C, int n, float* sh) {
    const int rowTiles = (n + 63) >> 6;
    const int ntiles = rowTiles * 2;
    float (*As)[68] = (float(*)[68])sh;              // [16][68]
    float (*Ws)[64] = (float(*)[64])(sh + 16 * 68);  // [16][64]
    int tid = threadIdx.x;
    int tn = tid & 15, tm = tid >> 4;
    for (int t = blockIdx.x; t < ntiles; t += NBLK) {
        int row0 = (t % rowTiles) << 6;
        int col0 = (t / rowTiles) << 6;
        float acc[4][4] = {};
        for (int k0 = 0; k0 < 128; k0 += 16) {
            #pragma unroll
            for (int l = tid; l < 64 * 16; l += NTHR) {
                int m = l >> 4, k = l & 15;
                int r = row0 + m;
                As[k][m] = (r < n) ? A[(size_t)r * 128 + k0 + k] : 0.f;
            }
            #pragma unroll
            for (int l = tid; l < 16 * 64; l += NTHR) {
                int k = l >> 6, c = l & 63;
                Ws[k][c] = W[(size_t)(k0 + k) * 128 + col0 + c];
            }
            __syncthreads();
            #pragma unroll
            for (int kk = 0; kk < 16; kk++) {
                float a[4], b[4];
                #pragma unroll
                for (int i = 0; i < 4; i++) a[i] = As[kk][tm * 4 + i];
                #pragma unroll
                for (int j = 0; j < 4; j++) b[j] = Ws[kk][tn * 4 + j];
                #pragma unroll
                for (int i = 0; i < 4; i++)
                    #pragma unroll
                    for (int j = 0; j < 4; j++)
                        acc[i][j] += a[i] * b[j];
            }
            __syncthreads();
        }
        #pragma unroll
        for (int i = 0; i < 4; i++) {
            int r = row0 + tm * 4 + i;
            if (r >= n) continue;
            #pragma unroll
            for (int j = 0; j < 4; j++)
                C[(size_t)r * 128 + col0 + tn * 4 + j] = acc[i][j];
        }
    }
}

// ---------------------------------------------------------------------------
// Aggregate (F=128), warp-per-node, x4 MLP unroll. Optional LN epilogue.
template<bool DO_LN>
__device__ void agg_phase(const float* __restrict__ h, const float* __restrict__ resid,
                          const float* __restrict__ bias, const float* __restrict__ gam,
                          const float* __restrict__ bet, float* __restrict__ outp,
                          int n, int gwarp, int lane) {
    for (int node = gwarp; node < n; node += NWARP) {
        float wl = 1.f / (float)(g_deg[node] + 1);
        float4 t = ((const float4*)(h + (size_t)node * HID))[lane];
        float4 acc = make_float4(t.x * wl, t.y * wl, t.z * wl, t.w * wl);
        int start = g_rowptr[node], end = g_rowptr[node + 1];
        for (int e0 = start; e0 < end; e0 += 32) {
            int e = e0 + lane;
            int2 rec = (e < end) ? g_edge[e] : make_int2(0, 0);
            int cnt = min(32, end - e0);
            int j = 0;
            for (; j + 4 <= cnt; j += 4) {
                int   s0 = __shfl_sync(0xffffffffu, rec.x, j);
                int   s1 = __shfl_sync(0xffffffffu, rec.x, j + 1);
                int   s2 = __shfl_sync(0xffffffffu, rec.x, j + 2);
                int   s3 = __shfl_sync(0xffffffffu, rec.x, j + 3);
                float w0 = __int_as_float(__shfl_sync(0xffffffffu, rec.y, j));
                float w1 = __int_as_float(__shfl_sync(0xffffffffu, rec.y, j + 1));
                float w2 = __int_as_float(__shfl_sync(0xffffffffu, rec.y, j + 2));
                float w3 = __int_as_float(__shfl_sync(0xffffffffu, rec.y, j + 3));
                float4 a0 = ((const float4*)(h + (size_t)s0 * HID))[lane];
                float4 a1 = ((const float4*)(h + (size_t)s1 * HID))[lane];
                float4 a2 = ((const float4*)(h + (size_t)s2 * HID))[lane];
                float4 a3 = ((const float4*)(h + (size_t)s3 * HID))[lane];
                acc.x += a0.x * w0 + a1.x * w1 + a2.x * w2 + a3.x * w3;
                acc.y += a0.y * w0 + a1.y * w1 + a2.y * w2 + a3.y * w3;
                acc.z += a0.z * w0 + a1.z * w1 + a2.z * w2 + a3.z * w3;
                acc.w += a0.w * w0 + a1.w * w1 + a2.w * w2 + a3.w * w3;
            }
            for (; j < cnt; j++) {
                int   ss = __shfl_sync(0xffffffffu, rec.x, j);
                float ww = __int_as_float(__shfl_sync(0xffffffffu, rec.y, j));
                float4 a0 = ((const float4*)(h + (size_t)ss * HID))[lane];
                acc.x += a0.x * ww; acc.y += a0.y * ww;
                acc.z += a0.z * ww; acc.w += a0.w * ww;
            }
        }
        if (DO_LN) {
            float4 rr = ((const float4*)(resid + (size_t)node * HID))[lane];
            float4 b4 = ((const float4*)bias)[lane];
            acc.x += rr.x + b4.x; acc.y += rr.y + b4.y;
            acc.z += rr.z + b4.z; acc.w += rr.w + b4.w;
            float s  = acc.x + acc.y + acc.z + acc.w;
            float sq = acc.x*acc.x + acc.y*acc.y + acc.z*acc.z + acc.w*acc.w;
            #pragma unroll
            for (int off = 16; off > 0; off >>= 1) {
                s  += __shfl_xor_sync(0xffffffffu, s,  off);
                sq += __shfl_xor_sync(0xffffffffu, sq, off);
            }
            float mu  = s * (1.f / HID);
            float var = sq * (1.f / HID) - mu * mu;
            float rs  = rsqrtf(var + 1e-5f);
            float4 g4 = ((const float4*)gam)[lane];
            float4 l4 = ((const float4*)bet)[lane];
            acc.x = fmaxf(0.f, (acc.x - mu) * rs * g4.x + l4.x);
            acc.y = fmaxf(0.f, (acc.y - mu) * rs * g4.y + l4.y);
            acc.z = fmaxf(0.f, (acc.z - mu) * rs * g4.z + l4.z);
            acc.w = fmaxf(0.f, (acc.w - mu) * rs * g4.w + l4.w);
        }
        ((float4*)(outp + (size_t)node * HID))[lane] = acc;
    }
}

// ---------------------------------------------------------------------------
__global__ void __launch_bounds__(NTHR, 3) mega_kernel(
    const float* __restrict__ x, const int* __restrict__ src,
    const int* __restrict__ dst, const int* __restrict__ batch,
    const float* __restrict__ W1, const float* __restrict__ b1,
    const float* __restrict__ W2, const float* __restrict__ b2,
    const float* __restrict__ W3, const float* __restrict__ b3,
    const float* __restrict__ rW, const float* __restrict__ rb,
    const float* __restrict__ g1, const float* __restrict__ be1,
    const float* __restrict__ g2, const float* __restrict__ be2,
    float* __restrict__ out, int n, int e)
{
    __shared__ float sh[5248];
    unsigned ls = 0;
    const int tid  = threadIdx.x;
    const int gtid = blockIdx.x * NTHR + tid;
    const int gstr = NBLK * NTHR;
    const int lane = tid & 31, wid = tid >> 5;
    const int gwarp = blockIdx.x * 8 + wid;

    // ---- P0: zero ----
    for (int i = gtid; i < n; i += gstr) g_deg[i] = 0;
    if (gtid < NB) g_cnt[gtid] = 0;
    for (int i = gtid; i < NB * HID; i += gstr) g_pool[i] = 0.f;
    grid_barrier(ls);                                            // B1

    // ---- P1: histograms ----
    for (int i = gtid; i < e; i += gstr) atomicAdd(&g_deg[dst[i]], 1);
    for (int i = gtid; i < n; i += gstr) atomicAdd(&g_cnt[batch[i]], 1);
    grid_barrier(ls);                                            // B2

    // ---- P2: block 0 scans deg->rowptr/cursor; blocks 1..443 do input GEMMs ----
    if (blockIdx.x == 0) {
        int* wsum = (int*)sh;
        int carry = 0;
        for (int base = 0; base < n; base += NTHR) {
            int i = base + tid;
            int v = (i < n) ? g_deg[i] : 0;
            int xv = v;
            #pragma unroll
            for (int off = 1; off < 32; off <<= 1) {
                int t = __shfl_up_sync(0xffffffffu, xv, off);
                if (lane >= off) xv += t;
            }
            if (lane == 31) wsum[wid] = xv;
            __syncthreads();
            if (wid == 0) {
                int sv = (lane < 8) ? wsum[lane] : 0;
                #pragma unroll
                for (int off = 1; off < 8; off <<= 1) {
                    int t = __shfl_up_sync(0xffffffffu, sv, off);
                    if (lane >= off) sv += t;
                }
                if (lane < 8) wsum[lane] = sv;
            }
            __syncthreads();
            int excl = carry + (wid ? wsum[wid - 1] : 0) + xv - v;
            if (i < n) { g_rowptr[i] = excl; g_cursor[i] = excl; }
            int total = wsum[7];
            __syncthreads();
            carry += total;
        }
        if (tid == 0) g_rowptr[n] = carry;
    } else {
        float* sW1 = sh;            // 2560
        float* sRW = sh + 2560;     // 2560
        float* sRB = sh + 5120;     // 128
        for (int i = tid; i < 20 * 128; i += NTHR) { sW1[i] = W1[i]; sRW[i] = rW[i]; }
        if (tid < 128) sRB[tid] = rb[tid];
        __syncthreads();
        int w2 = (blockIdx.x - 1) * 8 + wid;
        for (int row = w2; row < n; row += (NBLK - 1) * 8) {
            float xv = (lane < 20) ? x[(size_t)row * 20 + lane] : 0.f;
            float4 a = make_float4(0.f, 0.f, 0.f, 0.f);
            float4 r = make_float4(0.f, 0.f, 0.f, 0.f);
            #pragma unroll
            for (int k = 0; k < 20; k++) {
                float xk = __shfl_sync(0xffffffffu, xv, k);
                float4 w = ((const float4*)(sW1 + k * 128))[lane];
                a.x += xk * w.x; a.y += xk * w.y; a.z += xk * w.z; a.w += xk * w.w;
                float4 v = ((const float4*)(sRW + k * 128))[lane];
                r.x += xk * v.x; r.y += xk * v.y; r.z += xk * v.z; r.w += xk * v.w;
            }
            float4 rb4 = ((const float4*)sRB)[lane];
            r.x += rb4.x; r.y += rb4.y; r.z += rb4.z; r.w += rb4.w;
            ((float4*)(g_bufA + (size_t)row * HID))[lane] = a;
            ((float4*)(g_res  + (size_t)row * HID))[lane] = r;
        }
    }
    grid_barrier(ls);                                            // B3

    // ---- P3: csr fill ----
    for (int i = gtid; i < e; i += gstr) {
        int s = src[i], d = dst[i];
        int pos = atomicAdd(&g_cursor[d], 1);
        float nrm = rsqrtf((float)(g_deg[s] + 1) * (float)(g_deg[d] + 1));
        g_edge[pos] = make_int2(s, __float_as_int(nrm));
    }
    grid_barrier(ls);                                            // B4

    // ---- layer 1: aggregate + bias + residual + LN + ReLU ----
    agg_phase<true>(g_bufA, g_res, b1, g1, be1, g_hbuf, n, gwarp, lane);
    grid_barrier(ls);                                            // B5

    // ---- layer 2 GEMM ----
    gemm_phase128(g_hbuf, W2, g_bufA, n, sh);
    grid_barrier(ls);                                            // B6

    agg_phase<true>(g_bufA, g_hbuf, b2, g2, be2, g_res, n, gwarp, lane);
    grid_barrier(ls);                                            // B7

    // ---- layer 3: aggregate the 128-wide H (GEMM deferred past pooling) ----
    agg_phase<false>(g_res, nullptr, nullptr, nullptr, nullptr, g_bufA, n, gwarp, lane);
    grid_barrier(ls);                                            // B8

    // ---- pooling over 128-wide aggregated features (batch sorted) ----
    {
        int* sb = (int*)sh;
        int half = tid >> 7;          // 0 or 1: rows [0,64) or [64,128)
        int f = tid & 127;
        for (int c = blockIdx.x; c * 128 < n; c += NBLK) {
            int r0 = c * 128;
            int r1 = min(n, r0 + 128);
            __syncthreads();
            if (tid < r1 - r0) sb[tid] = batch[r0 + tid];
            __syncthreads();
            int rs = r0 + half * 64;
            int re = min(r1, rs + 64);
            if (rs < re) {
                int cur = sb[rs - r0];
                float acc = 0.f;
                for (int r = rs; r < re; r++) {
                    int g = sb[r - r0];
                    float val = g_bufA[(size_t)r * HID + f];
                    if (g != cur) { atomicAdd(&g_pool[cur * HID + f], acc); acc = 0.f; cur = g; }
                    acc += val;
                }
                atomicAdd(&g_pool[cur * HID + f], acc);
            }
        }
    }
    grid_barrier(ls);                                            // B9

    // ---- final: out[b,:] = (pool[b,:]/cnt[b]) @ W3 + b3 (blocks 0..63) ----
    if (blockIdx.x < NB) {
        int b = blockIdx.x;
        float* sp = sh;               // 128 floats
        float c = (float)g_cnt[b];
        float inv = (c > 0.f) ? 1.f / c : 0.f;
        if (tid < 128) sp[tid] = g_pool[b * HID + tid] * inv;
        __syncthreads();
        float acc = 0.f;
        #pragma unroll 8
        for (int k = 0; k < 128; k++)
            acc += sp[k] * W3[(size_t)k * OUTD + tid];
        out[b * OUTD + tid] = (c > 0.f) ? (acc + b3[tid]) : 0.f;
    }
    grid_barrier(ls);                                            // B10 (even count)
}

// ---------------------------------------------------------------------------
extern "C" void kernel_launch(void* const* d_in, const int* in_sizes, int n_in,
                              void* d_out, int out_size) {
    const float* x     = (const float*)d_in[0];
    const int*   ei    = (const int*)d_in[1];      // int32 (JAX x64 disabled)
    const int*   batch = (const int*)d_in[2];
    const float *W1 = (const float*)d_in[3],  *b1 = (const float*)d_in[4];
    const float *W2 = (const float*)d_in[5],  *b2 = (const float*)d_in[6];
    const float *W3 = (const float*)d_in[7],  *b3 = (const float*)d_in[8];
    const float *rW = (const float*)d_in[9],  *rb = (const float*)d_in[10];
    const float *g1 = (const float*)d_in[11], *be1 = (const float*)d_in[12];
    const float *g2 = (const float*)d_in[13], *be2 = (const float*)d_in[14];
    float* out = (float*)d_out;

    int n = in_sizes[0] / 20;
    int e = in_sizes[1] / 2;
    const int* src = ei;
    const int* dst = ei + e;

    mega_kernel<<<NBLK, NTHR>>>(x, src, dst, batch,
                                W1, b1, W2, b2, W3, b3, rW, rb,
                                g1, be1, g2, be2, out, n, e);
}

// round 7
// speedup vs baseline: 31.3550x; 1.1056x over previous
#include <cuda_runtime.h>
#include <cuda_bf16.h>

// ---------------------------------------------------------------------------
// BaseGNN: 3-layer GCN, N=100000, E=1.6M, B=64. Persistent mega-kernel.
// R6: 915us (occ 36.5%, issue 18% -> latency bound). R7: occupancy push —
// launch_bounds(256,4), 592 blocks (4/SM, regs<=64), GEMM BK=32 (half the
// syncthreads). 10 grid barriers (even -> sense self-resets per replay).
// ---------------------------------------------------------------------------

#define N_MAX 100000
#define E_MAX 1600000
#define NB    64
#define HID   128
#define OUTD  256
#define NBLK  592
#define NTHR  256
#define NWARP (NBLK * 8)

__device__ int   g_deg[N_MAX];
__device__ int   g_rowptr[N_MAX + 1];
__device__ int   g_cursor[N_MAX];
__device__ int2  g_edge[E_MAX];          // {src, float-bits(norm)}
__device__ float g_bufA[(size_t)N_MAX * HID];
__device__ float g_res [(size_t)N_MAX * HID];
__device__ float g_hbuf[(size_t)N_MAX * HID];
__device__ float g_pool[NB * HID];
__device__ int   g_cnt[NB];
__device__ unsigned g_bar_count = 0;
__device__ unsigned g_bar_sense = 0;

// sense-reversing software grid barrier (all NBLK blocks co-resident).
__device__ __forceinline__ void grid_barrier(unsigned& ls) {
    __threadfence();
    __syncthreads();
    ls ^= 1u;
    if (threadIdx.x == 0) {
        unsigned arrived = atomicAdd(&g_bar_count, 1u);
        if (arrived == NBLK - 1u) {
            atomicExch(&g_bar_count, 0u);
            __threadfence();
            atomicExch(&g_bar_sense, ls);
        } else {
            while (((volatile unsigned*)&g_bar_sense)[0] != ls) __nanosleep(64);
            __threadfence();
        }
    }
    __syncthreads();
}

// ---------------------------------------------------------------------------
// GEMM phase: C[n,128] = A[n,128] @ W[128,128]; 64x64 tiles, BK=32.
__device__ void gemm_phase128(const float* __restrict__ A, const float* __restrict__ W,
                              float* __restrict__ C, int n, float* sh) {
    const int rowTiles = (n + 63) >> 6;
    const int ntiles = rowTiles * 2;
    float (*As)[68] = (float(*)[68])sh;              // [32][68]
    float (*Ws)[64] = (float(*)[64])(sh + 32 * 68);  // [32][64]
    int tid = threadIdx.x;
    int tn = tid & 15, tm = tid >> 4;
    for (int t = blockIdx.x; t < ntiles; t += NBLK) {
        int row0 = (t % rowTiles) << 6;
        int col0 = (t / rowTiles) << 6;
        float acc[4][4] = {};
        #pragma unroll
        for (int k0 = 0; k0 < 128; k0 += 32) {
            #pragma unroll
            for (int l = tid; l < 64 * 32; l += NTHR) {
                int m = l >> 5, k = l & 31;
                int r = row0 + m;
                As[k][m] = (r < n) ? A[(size_t)r * 128 + k0 + k] : 0.f;
            }
            #pragma unroll
            for (int l = tid; l < 32 * 64; l += NTHR) {
                int k = l >> 6, c = l & 63;
                Ws[k][c] = W[(size_t)(k0 + k) * 128 + col0 + c];
            }
            __syncthreads();
            #pragma unroll
            for (int kk = 0; kk < 32; kk++) {
                float a[4], b[4];
                #pragma unroll
                for (int i = 0; i < 4; i++) a[i] = As[kk][tm * 4 + i];
                #pragma unroll
                for (int j = 0; j < 4; j++) b[j] = Ws[kk][tn * 4 + j];
                #pragma unroll
                for (int i = 0; i < 4; i++)
                    #pragma unroll
                    for (int j = 0; j < 4; j++)
                        acc[i][j] += a[i] * b[j];
            }
            __syncthreads();
        }
        #pragma unroll
        for (int i = 0; i < 4; i++) {
            int r = row0 + tm * 4 + i;
            if (r >= n) continue;
            #pragma unroll
            for (int j = 0; j < 4; j++)
                C[(size_t)r * 128 + col0 + tn * 4 + j] = acc[i][j];
        }
    }
}

// ---------------------------------------------------------------------------
// Aggregate (F=128), warp-per-node, x4 MLP unroll. Optional LN epilogue.
template<bool DO_LN>
__device__ void agg_phase(const float* __restrict__ h, const float* __restrict__ resid,
                          const float* __restrict__ bias, const float* __restrict__ gam,
                          const float* __restrict__ bet, float* __restrict__ outp,
                          int n, int gwarp, int lane) {
    for (int node = gwarp; node < n; node += NWARP) {
        float wl = 1.f / (float)(g_deg[node] + 1);
        float4 t = ((const float4*)(h + (size_t)node * HID))[lane];
        float4 acc = make_float4(t.x * wl, t.y * wl, t.z * wl, t.w * wl);
        int start = g_rowptr[node], end = g_rowptr[node + 1];
        for (int e0 = start; e0 < end; e0 += 32) {
            int e = e0 + lane;
            int2 rec = (e < end) ? g_edge[e] : make_int2(0, 0);
            int cnt = min(32, end - e0);
            int j = 0;
            for (; j + 4 <= cnt; j += 4) {
                int   s0 = __shfl_sync(0xffffffffu, rec.x, j);
                int   s1 = __shfl_sync(0xffffffffu, rec.x, j + 1);
                int   s2 = __shfl_sync(0xffffffffu, rec.x, j + 2);
                int   s3 = __shfl_sync(0xffffffffu, rec.x, j + 3);
                float w0 = __int_as_float(__shfl_sync(0xffffffffu, rec.y, j));
                float w1 = __int_as_float(__shfl_sync(0xffffffffu, rec.y, j + 1));
                float w2 = __int_as_float(__shfl_sync(0xffffffffu, rec.y, j + 2));
                float w3 = __int_as_float(__shfl_sync(0xffffffffu, rec.y, j + 3));
                float4 a0 = ((const float4*)(h + (size_t)s0 * HID))[lane];
                float4 a1 = ((const float4*)(h + (size_t)s1 * HID))[lane];
                float4 a2 = ((const float4*)(h + (size_t)s2 * HID))[lane];
                float4 a3 = ((const float4*)(h + (size_t)s3 * HID))[lane];
                acc.x += a0.x * w0 + a1.x * w1 + a2.x * w2 + a3.x * w3;
                acc.y += a0.y * w0 + a1.y * w1 + a2.y * w2 + a3.y * w3;
                acc.z += a0.z * w0 + a1.z * w1 + a2.z * w2 + a3.z * w3;
                acc.w += a0.w * w0 + a1.w * w1 + a2.w * w2 + a3.w * w3;
            }
            for (; j < cnt; j++) {
                int   ss = __shfl_sync(0xffffffffu, rec.x, j);
                float ww = __int_as_float(__shfl_sync(0xffffffffu, rec.y, j));
                float4 a0 = ((const float4*)(h + (size_t)ss * HID))[lane];
                acc.x += a0.x * ww; acc.y += a0.y * ww;
                acc.z += a0.z * ww; acc.w += a0.w * ww;
            }
        }
        if (DO_LN) {
            float4 rr = ((const float4*)(resid + (size_t)node * HID))[lane];
            float4 b4 = ((const float4*)bias)[lane];
            acc.x += rr.x + b4.x; acc.y += rr.y + b4.y;
            acc.z += rr.z + b4.z; acc.w += rr.w + b4.w;
            float s  = acc.x + acc.y + acc.z + acc.w;
            float sq = acc.x*acc.x + acc.y*acc.y + acc.z*acc.z + acc.w*acc.w;
            #pragma unroll
            for (int off = 16; off > 0; off >>= 1) {
                s  += __shfl_xor_sync(0xffffffffu, s,  off);
                sq += __shfl_xor_sync(0xffffffffu, sq, off);
            }
            float mu  = s * (1.f / HID);
            float var = sq * (1.f / HID) - mu * mu;
            float rs  = rsqrtf(var + 1e-5f);
            float4 g4 = ((const float4*)gam)[lane];
            float4 l4 = ((const float4*)bet)[lane];
            acc.x = fmaxf(0.f, (acc.x - mu) * rs * g4.x + l4.x);
            acc.y = fmaxf(0.f, (acc.y - mu) * rs * g4.y + l4.y);
            acc.z = fmaxf(0.f, (acc.z - mu) * rs * g4.z + l4.z);
            acc.w = fmaxf(0.f, (acc.w - mu) * rs * g4.w + l4.w);
        }
        ((float4*)(outp + (size_t)node * HID))[lane] = acc;
    }
}

// ---------------------------------------------------------------------------
__global__ void __launch_bounds__(NTHR, 4) mega_kernel(
    const float* __restrict__ x, const int* __restrict__ src,
    const int* __restrict__ dst, const int* __restrict__ batch,
    const float* __restrict__ W1, const float* __restrict__ b1,
    const float* __restrict__ W2, const float* __restrict__ b2,
    const float* __restrict__ W3, const float* __restrict__ b3,
    const float* __restrict__ rW, const float* __restrict__ rb,
    const float* __restrict__ g1, const float* __restrict__ be1,
    const float* __restrict__ g2, const float* __restrict__ be2,
    float* __restrict__ out, int n, int e)
{
    __shared__ float sh[5248];
    unsigned ls = 0;
    const int tid  = threadIdx.x;
    const int gtid = blockIdx.x * NTHR + tid;
    const int gstr = NBLK * NTHR;
    const int lane = tid & 31, wid = tid >> 5;
    const int gwarp = blockIdx.x * 8 + wid;

    // ---- P0: zero ----
    for (int i = gtid; i < n; i += gstr) g_deg[i] = 0;
    if (gtid < NB) g_cnt[gtid] = 0;
    for (int i = gtid; i < NB * HID; i += gstr) g_pool[i] = 0.f;
    grid_barrier(ls);                                            // B1

    // ---- P1: histograms ----
    for (int i = gtid; i < e; i += gstr) atomicAdd(&g_deg[dst[i]], 1);
    for (int i = gtid; i < n; i += gstr) atomicAdd(&g_cnt[batch[i]], 1);
    grid_barrier(ls);                                            // B2

    // ---- P2: block 0 scans; other blocks do the fused input GEMMs ----
    if (blockIdx.x == 0) {
        int* wsum = (int*)sh;
        int carry = 0;
        for (int base = 0; base < n; base += NTHR) {
            int i = base + tid;
            int v = (i < n) ? g_deg[i] : 0;
            int xv = v;
            #pragma unroll
            for (int off = 1; off < 32; off <<= 1) {
                int t = __shfl_up_sync(0xffffffffu, xv, off);
                if (lane >= off) xv += t;
            }
            if (lane == 31) wsum[wid] = xv;
            __syncthreads();
            if (wid == 0) {
                int sv = (lane < 8) ? wsum[lane] : 0;
                #pragma unroll
                for (int off = 1; off < 8; off <<= 1) {
                    int t = __shfl_up_sync(0xffffffffu, sv, off);
                    if (lane >= off) sv += t;
                }
                if (lane < 8) wsum[lane] = sv;
            }
            __syncthreads();
            int excl = carry + (wid ? wsum[wid - 1] : 0) + xv - v;
            if (i < n) { g_rowptr[i] = excl; g_cursor[i] = excl; }
            int total = wsum[7];
            __syncthreads();
            carry += total;
        }
        if (tid == 0) g_rowptr[n] = carry;
    } else {
        float* sW1 = sh;            // 2560
        float* sRW = sh + 2560;     // 2560
        float* sRB = sh + 5120;     // 128
        for (int i = tid; i < 20 * 128; i += NTHR) { sW1[i] = W1[i]; sRW[i] = rW[i]; }
        if (tid < 128) sRB[tid] = rb[tid];
        __syncthreads();
        int w2 = (blockIdx.x - 1) * 8 + wid;
        for (int row = w2; row < n; row += (NBLK - 1) * 8) {
            float xv = (lane < 20) ? x[(size_t)row * 20 + lane] : 0.f;
            float4 a = make_float4(0.f, 0.f, 0.f, 0.f);
            float4 r = make_float4(0.f, 0.f, 0.f, 0.f);
            #pragma unroll
            for (int k = 0; k < 20; k++) {
                float xk = __shfl_sync(0xffffffffu, xv, k);
                float4 w = ((const float4*)(sW1 + k * 128))[lane];
                a.x += xk * w.x; a.y += xk * w.y; a.z += xk * w.z; a.w += xk * w.w;
                float4 v = ((const float4*)(sRW + k * 128))[lane];
                r.x += xk * v.x; r.y += xk * v.y; r.z += xk * v.z; r.w += xk * v.w;
            }
            float4 rb4 = ((const float4*)sRB)[lane];
            r.x += rb4.x; r.y += rb4.y; r.z += rb4.z; r.w += rb4.w;
            ((float4*)(g_bufA + (size_t)row * HID))[lane] = a;
            ((float4*)(g_res  + (size_t)row * HID))[lane] = r;
        }
    }
    grid_barrier(ls);                                            // B3

    // ---- P3: csr fill ----
    for (int i = gtid; i < e; i += gstr) {
        int s = src[i], d = dst[i];
        int pos = atomicAdd(&g_cursor[d], 1);
        float nrm = rsqrtf((float)(g_deg[s] + 1) * (float)(g_deg[d] + 1));
        g_edge[pos] = make_int2(s, __float_as_int(nrm));
    }
    grid_barrier(ls);                                            // B4

    // ---- layer 1: aggregate + bias + residual + LN + ReLU ----
    agg_phase<true>(g_bufA, g_res, b1, g1, be1, g_hbuf, n, gwarp, lane);
    grid_barrier(ls);                                            // B5

    // ---- layer 2 GEMM ----
    gemm_phase128(g_hbuf, W2, g_bufA, n, sh);
    grid_barrier(ls);                                            // B6

    agg_phase<true>(g_bufA, g_hbuf, b2, g2, be2, g_res, n, gwarp, lane);
    grid_barrier(ls);                                            // B7

    // ---- layer 3: aggregate the 128-wide H (GEMM deferred past pooling) ----
    agg_phase<false>(g_res, nullptr, nullptr, nullptr, nullptr, g_bufA, n, gwarp, lane);
    grid_barrier(ls);                                            // B8

    // ---- pooling over 128-wide aggregated features (batch sorted) ----
    {
        int* sb = (int*)sh;
        int half = tid >> 7;          // 0 or 1: rows [0,64) or [64,128)
        int f = tid & 127;
        for (int c = blockIdx.x; c * 128 < n; c += NBLK) {
            int r0 = c * 128;
            int r1 = min(n, r0 + 128);
            __syncthreads();
            if (tid < r1 - r0) sb[tid] = batch[r0 + tid];
            __syncthreads();
            int rs = r0 + half * 64;
            int re = min(r1, rs + 64);
            if (rs < re) {
                int cur = sb[rs - r0];
                float acc = 0.f;
                for (int r = rs; r < re; r++) {
                    int g = sb[r - r0];
                    float val = g_bufA[(size_t)r * HID + f];
                    if (g != cur) { atomicAdd(&g_pool[cur * HID + f], acc); acc = 0.f; cur = g; }
                    acc += val;
                }
                atomicAdd(&g_pool[cur * HID + f], acc);
            }
        }
    }
    grid_barrier(ls);                                            // B9

    // ---- final: out[b,:] = (pool[b,:]/cnt[b]) @ W3 + b3 (blocks 0..63) ----
    if (blockIdx.x < NB) {
        int b = blockIdx.x;
        float* sp = sh;               // 128 floats
        float c = (float)g_cnt[b];
        float inv = (c > 0.f) ? 1.f / c : 0.f;
        if (tid < 128) sp[tid] = g_pool[b * HID + tid] * inv;
        __syncthreads();
        float acc = 0.f;
        #pragma unroll 8
        for (int k = 0; k < 128; k++)
            acc += sp[k] * W3[(size_t)k * OUTD + tid];
        out[b * OUTD + tid] = (c > 0.f) ? (acc + b3[tid]) : 0.f;
    }
    grid_barrier(ls);                                            // B10 (even count)
}

// ---------------------------------------------------------------------------
extern "C" void kernel_launch(void* const* d_in, const int* in_sizes, int n_in,
                              void* d_out, int out_size) {
    const float* x     = (const float*)d_in[0];
    const int*   ei    = (const int*)d_in[1];      // int32 (JAX x64 disabled)
    const int*   batch = (const int*)d_in[2];
    const float *W1 = (const float*)d_in[3],  *b1 = (const float*)d_in[4];
    const float *W2 = (const float*)d_in[5],  *b2 = (const float*)d_in[6];
    const float *W3 = (const float*)d_in[7],  *b3 = (const float*)d_in[8];
    const float *rW = (const float*)d_in[9],  *rb = (const float*)d_in[10];
    const float *g1 = (const float*)d_in[11], *be1 = (const float*)d_in[12];
    const float *g2 = (const float*)d_in[13], *be2 = (const float*)d_in[14];
    float* out = (float*)d_out;

    int n = in_sizes[0] / 20;
    int e = in_sizes[1] / 2;
    const int* src = ei;
    const int* dst = ei + e;

    mega_kernel<<<NBLK, NTHR>>>(x, src, dst, batch,
                                W1, b1, W2, b2, W3, b3, rW, rb,
                                g1, be1, g2, be2, out, n, e);
}

// round 8
// speedup vs baseline: 43.6431x; 1.3919x over previous
#include <cuda_runtime.h>
#include <cuda_bf16.h>

// ---------------------------------------------------------------------------
// BaseGNN: 3-layer GCN, N=100000, E=1.6M, B=64. Persistent mega-kernel.
// R7: 827us (occ 49%, issue 20% -> per-warp latency chains bind). R8:
// agg unroll x8 (MLP 8), agg3 fused with pooling (contiguous chunks +
// register pool accumulator), 4-elem/thread scan, vectorized GEMM loads.
// 8 grid barriers (even -> sense self-resets per replay).
// ---------------------------------------------------------------------------

#define N_MAX 100000
#define E_MAX 1600000
#define NB    64
#define HID   128
#define OUTD  256
#define NBLK  592
#define NTHR  256
#define NWARP (NBLK * 8)

__device__ int   g_deg[N_MAX];
__device__ int   g_rowptr[N_MAX + 1];
__device__ int   g_cursor[N_MAX];
__device__ int2  g_edge[E_MAX];          // {src, float-bits(norm)}
__device__ float g_bufA[(size_t)N_MAX * HID];
__device__ float g_res [(size_t)N_MAX * HID];
__device__ float g_hbuf[(size_t)N_MAX * HID];
__device__ float g_pool[NB * HID];
__device__ int   g_cnt[NB];
__device__ unsigned g_bar_count = 0;
__device__ unsigned g_bar_sense = 0;

__device__ __forceinline__ void grid_barrier(unsigned& ls) {
    __threadfence();
    __syncthreads();
    ls ^= 1u;
    if (threadIdx.x == 0) {
        unsigned arrived = atomicAdd(&g_bar_count, 1u);
        if (arrived == NBLK - 1u) {
            atomicExch(&g_bar_count, 0u);
            __threadfence();
            atomicExch(&g_bar_sense, ls);
        } else {
            while (((volatile unsigned*)&g_bar_sense)[0] != ls) __nanosleep(64);
            __threadfence();
        }
    }
    __syncthreads();
}

// ---------------------------------------------------------------------------
// Gather-accumulate one node's neighborhood into acc (float4 per lane).
__device__ __forceinline__ void gather_node(const float* __restrict__ h, int node,
                                            int lane, float4& acc) {
    float wl = 1.f / (float)(g_deg[node] + 1);
    float4 t = ((const float4*)(h + (size_t)node * HID))[lane];
    acc.x += t.x * wl; acc.y += t.y * wl; acc.z += t.z * wl; acc.w += t.w * wl;
    int start = g_rowptr[node], end = g_rowptr[node + 1];
    for (int e0 = start; e0 < end; e0 += 32) {
        int e = e0 + lane;
        int2 rec = (e < end) ? g_edge[e] : make_int2(0, 0);
        int cnt = min(32, end - e0);
        int j = 0;
        for (; j + 8 <= cnt; j += 8) {
            int s0 = __shfl_sync(0xffffffffu, rec.x, j);
            int s1 = __shfl_sync(0xffffffffu, rec.x, j + 1);
            int s2 = __shfl_sync(0xffffffffu, rec.x, j + 2);
            int s3 = __shfl_sync(0xffffffffu, rec.x, j + 3);
            int s4 = __shfl_sync(0xffffffffu, rec.x, j + 4);
            int s5 = __shfl_sync(0xffffffffu, rec.x, j + 5);
            int s6 = __shfl_sync(0xffffffffu, rec.x, j + 6);
            int s7 = __shfl_sync(0xffffffffu, rec.x, j + 7);
            float w0 = __int_as_float(__shfl_sync(0xffffffffu, rec.y, j));
            float w1 = __int_as_float(__shfl_sync(0xffffffffu, rec.y, j + 1));
            float w2 = __int_as_float(__shfl_sync(0xffffffffu, rec.y, j + 2));
            float w3 = __int_as_float(__shfl_sync(0xffffffffu, rec.y, j + 3));
            float w4 = __int_as_float(__shfl_sync(0xffffffffu, rec.y, j + 4));
            float w5 = __int_as_float(__shfl_sync(0xffffffffu, rec.y, j + 5));
            float w6 = __int_as_float(__shfl_sync(0xffffffffu, rec.y, j + 6));
            float w7 = __int_as_float(__shfl_sync(0xffffffffu, rec.y, j + 7));
            float4 a0 = ((const float4*)(h + (size_t)s0 * HID))[lane];
            float4 a1 = ((const float4*)(h + (size_t)s1 * HID))[lane];
            float4 a2 = ((const float4*)(h + (size_t)s2 * HID))[lane];
            float4 a3 = ((const float4*)(h + (size_t)s3 * HID))[lane];
            float4 a4 = ((const float4*)(h + (size_t)s4 * HID))[lane];
            float4 a5 = ((const float4*)(h + (size_t)s5 * HID))[lane];
            float4 a6 = ((const float4*)(h + (size_t)s6 * HID))[lane];
            float4 a7 = ((const float4*)(h + (size_t)s7 * HID))[lane];
            float px = a0.x * w0 + a1.x * w1 + a2.x * w2 + a3.x * w3;
            float py = a0.y * w0 + a1.y * w1 + a2.y * w2 + a3.y * w3;
            float pz = a0.z * w0 + a1.z * w1 + a2.z * w2 + a3.z * w3;
            float pw = a0.w * w0 + a1.w * w1 + a2.w * w2 + a3.w * w3;
            px += a4.x * w4 + a5.x * w5 + a6.x * w6 + a7.x * w7;
            py += a4.y * w4 + a5.y * w5 + a6.y * w6 + a7.y * w7;
            pz += a4.z * w4 + a5.z * w5 + a6.z * w6 + a7.z * w7;
            pw += a4.w * w4 + a5.w * w5 + a6.w * w6 + a7.w * w7;
            acc.x += px; acc.y += py; acc.z += pz; acc.w += pw;
        }
        for (; j + 4 <= cnt; j += 4) {
            int s0 = __shfl_sync(0xffffffffu, rec.x, j);
            int s1 = __shfl_sync(0xffffffffu, rec.x, j + 1);
            int s2 = __shfl_sync(0xffffffffu, rec.x, j + 2);
            int s3 = __shfl_sync(0xffffffffu, rec.x, j + 3);
            float w0 = __int_as_float(__shfl_sync(0xffffffffu, rec.y, j));
            float w1 = __int_as_float(__shfl_sync(0xffffffffu, rec.y, j + 1));
            float w2 = __int_as_float(__shfl_sync(0xffffffffu, rec.y, j + 2));
            float w3 = __int_as_float(__shfl_sync(0xffffffffu, rec.y, j + 3));
            float4 a0 = ((const float4*)(h + (size_t)s0 * HID))[lane];
            float4 a1 = ((const float4*)(h + (size_t)s1 * HID))[lane];
            float4 a2 = ((const float4*)(h + (size_t)s2 * HID))[lane];
            float4 a3 = ((const float4*)(h + (size_t)s3 * HID))[lane];
            acc.x += a0.x * w0 + a1.x * w1 + a2.x * w2 + a3.x * w3;
            acc.y += a0.y * w0 + a1.y * w1 + a2.y * w2 + a3.y * w3;
            acc.z += a0.z * w0 + a1.z * w1 + a2.z * w2 + a3.z * w3;
            acc.w += a0.w * w0 + a1.w * w1 + a2.w * w2 + a3.w * w3;
        }
        for (; j < cnt; j++) {
            int   ss = __shfl_sync(0xffffffffu, rec.x, j);
            float ww = __int_as_float(__shfl_sync(0xffffffffu, rec.y, j));
            float4 a0 = ((const float4*)(h + (size_t)ss * HID))[lane];
            acc.x += a0.x * ww; acc.y += a0.y * ww;
            acc.z += a0.z * ww; acc.w += a0.w * ww;
        }
    }
}

// Aggregate + bias + residual + LN + ReLU, warp-per-node (strided).
__device__ void agg_ln_phase(const float* __restrict__ h, const float* __restrict__ resid,
                             const float* __restrict__ bias, const float* __restrict__ gam,
                             const float* __restrict__ bet, float* __restrict__ outp,
                             int n, int gwarp, int lane) {
    for (int node = gwarp; node < n; node += NWARP) {
        float4 acc = make_float4(0.f, 0.f, 0.f, 0.f);
        gather_node(h, node, lane, acc);
        float4 rr = ((const float4*)(resid + (size_t)node * HID))[lane];
        float4 b4 = ((const float4*)bias)[lane];
        acc.x += rr.x + b4.x; acc.y += rr.y + b4.y;
        acc.z += rr.z + b4.z; acc.w += rr.w + b4.w;
        float s  = acc.x + acc.y + acc.z + acc.w;
        float sq = acc.x*acc.x + acc.y*acc.y + acc.z*acc.z + acc.w*acc.w;
        #pragma unroll
        for (int off = 16; off > 0; off >>= 1) {
            s  += __shfl_xor_sync(0xffffffffu, s,  off);
            sq += __shfl_xor_sync(0xffffffffu, sq, off);
        }
        float mu  = s * (1.f / HID);
        float var = sq * (1.f / HID) - mu * mu;
        float rs  = rsqrtf(var + 1e-5f);
        float4 g4 = ((const float4*)gam)[lane];
        float4 l4 = ((const float4*)bet)[lane];
        acc.x = fmaxf(0.f, (acc.x - mu) * rs * g4.x + l4.x);
        acc.y = fmaxf(0.f, (acc.y - mu) * rs * g4.y + l4.y);
        acc.z = fmaxf(0.f, (acc.z - mu) * rs * g4.z + l4.z);
        acc.w = fmaxf(0.f, (acc.w - mu) * rs * g4.w + l4.w);
        ((float4*)(outp + (size_t)node * HID))[lane] = acc;
    }
}

// ---------------------------------------------------------------------------
// GEMM phase: C[n,128] = A[n,128] @ W[128,128]; 64x64 tiles, BK=32.
__device__ void gemm_phase128(const float* __restrict__ A, const float* __restrict__ W,
                              float* __restrict__ C, int n, float* sh) {
    const int rowTiles = (n + 63) >> 6;
    const int ntiles = rowTiles * 2;
    float (*As)[68] = (float(*)[68])sh;              // [32][68]
    float (*Ws)[64] = (float(*)[64])(sh + 32 * 68);  // [32][64]
    int tid = threadIdx.x;
    int tn = tid & 15, tm = tid >> 4;
    for (int t = blockIdx.x; t < ntiles; t += NBLK) {
        int row0 = (t % rowTiles) << 6;
        int col0 = (t / rowTiles) << 6;
        float acc[4][4] = {};
        #pragma unroll
        for (int k0 = 0; k0 < 128; k0 += 32) {
            // A: 64 rows x 8 float4 = 512 vec loads, 2 per thread
            #pragma unroll
            for (int l = tid; l < 64 * 8; l += NTHR) {
                int m = l >> 3, k4 = l & 7;
                int r = row0 + m;
                float4 v = (r < n) ? ((const float4*)(A + (size_t)r * 128 + k0))[k4]
                                   : make_float4(0.f, 0.f, 0.f, 0.f);
                As[k4 * 4 + 0][m] = v.x;
                As[k4 * 4 + 1][m] = v.y;
                As[k4 * 4 + 2][m] = v.z;
                As[k4 * 4 + 3][m] = v.w;
            }
            // W: 32 k-rows x 16 float4, 2 per thread, vectorized store
            #pragma unroll
            for (int l = tid; l < 32 * 16; l += NTHR) {
                int k = l >> 4, c4 = l & 15;
                float4 v = ((const float4*)(W + (size_t)(k0 + k) * 128 + col0))[c4];
                ((float4*)&Ws[k][c4 * 4])[0] = v;
            }
            __syncthreads();
            #pragma unroll
            for (int kk = 0; kk < 32; kk++) {
                float a[4], b[4];
                #pragma unroll
                for (int i = 0; i < 4; i++) a[i] = As[kk][tm * 4 + i];
                #pragma unroll
                for (int j = 0; j < 4; j++) b[j] = Ws[kk][tn * 4 + j];
                #pragma unroll
                for (int i = 0; i < 4; i++)
                    #pragma unroll
                    for (int j = 0; j < 4; j++)
                        acc[i][j] += a[i] * b[j];
            }
            __syncthreads();
        }
        #pragma unroll
        for (int i = 0; i < 4; i++) {
            int r = row0 + tm * 4 + i;
            if (r >= n) continue;
            #pragma unroll
            for (int j = 0; j < 4; j++)
                C[(size_t)r * 128 + col0 + tn * 4 + j] = acc[i][j];
        }
    }
}

// ---------------------------------------------------------------------------
__global__ void __launch_bounds__(NTHR, 4) mega_kernel(
    const float* __restrict__ x, const int* __restrict__ src,
    const int* __restrict__ dst, const int* __restrict__ batch,
    const float* __restrict__ W1, const float* __restrict__ b1,
    const float* __restrict__ W2, const float* __restrict__ b2,
    const float* __restrict__ W3, const float* __restrict__ b3,
    const float* __restrict__ rW, const float* __restrict__ rb,
    const float* __restrict__ g1, const float* __restrict__ be1,
    const float* __restrict__ g2, const float* __restrict__ be2,
    float* __restrict__ out, int n, int e)
{
    __shared__ float sh[5248];
    unsigned ls = 0;
    const int tid  = threadIdx.x;
    const int gtid = blockIdx.x * NTHR + tid;
    const int gstr = NBLK * NTHR;
    const int lane = tid & 31, wid = tid >> 5;
    const int gwarp = blockIdx.x * 8 + wid;

    // ---- P0: zero ----
    for (int i = gtid; i < n; i += gstr) g_deg[i] = 0;
    if (gtid < NB) g_cnt[gtid] = 0;
    for (int i = gtid; i < NB * HID; i += gstr) g_pool[i] = 0.f;
    grid_barrier(ls);                                            // B1

    // ---- P1: histograms ----
    for (int i = gtid; i < e; i += gstr) atomicAdd(&g_deg[dst[i]], 1);
    for (int i = gtid; i < n; i += gstr) atomicAdd(&g_cnt[batch[i]], 1);
    grid_barrier(ls);                                            // B2

    // ---- P2: block 0 scans (4 elems/thread); others do fused input GEMMs ----
    if (blockIdx.x == 0) {
        int* wsum = (int*)sh;
        int carry = 0;
        for (int base = 0; base < n; base += NTHR * 4) {
            int i0 = base + tid * 4;
            int v0 = (i0 + 0 < n) ? g_deg[i0 + 0] : 0;
            int v1 = (i0 + 1 < n) ? g_deg[i0 + 1] : 0;
            int v2 = (i0 + 2 < n) ? g_deg[i0 + 2] : 0;
            int v3 = (i0 + 3 < n) ? g_deg[i0 + 3] : 0;
            int tsum = v0 + v1 + v2 + v3;
            int xv = tsum;
            #pragma unroll
            for (int off = 1; off < 32; off <<= 1) {
                int t = __shfl_up_sync(0xffffffffu, xv, off);
                if (lane >= off) xv += t;
            }
            if (lane == 31) wsum[wid] = xv;
            __syncthreads();
            if (wid == 0) {
                int sv = (lane < 8) ? wsum[lane] : 0;
                #pragma unroll
                for (int off = 1; off < 8; off <<= 1) {
                    int t = __shfl_up_sync(0xffffffffu, sv, off);
                    if (lane >= off) sv += t;
                }
                if (lane < 8) wsum[lane] = sv;
            }
            __syncthreads();
            int excl = carry + (wid ? wsum[wid - 1] : 0) + xv - tsum;
            if (i0 + 0 < n) { g_rowptr[i0 + 0] = excl;             g_cursor[i0 + 0] = excl; }
            if (i0 + 1 < n) { g_rowptr[i0 + 1] = excl + v0;        g_cursor[i0 + 1] = excl + v0; }
            if (i0 + 2 < n) { g_rowptr[i0 + 2] = excl + v0 + v1;   g_cursor[i0 + 2] = excl + v0 + v1; }
            if (i0 + 3 < n) { g_rowptr[i0 + 3] = excl + v0 + v1 + v2; g_cursor[i0 + 3] = excl + v0 + v1 + v2; }
            int total = wsum[7];
            __syncthreads();
            carry += total;
        }
        if (tid == 0) g_rowptr[n] = carry;
    } else {
        float* sW1 = sh;            // 2560
        float* sRW = sh + 2560;     // 2560
        float* sRB = sh + 5120;     // 128
        for (int i = tid; i < 20 * 128; i += NTHR) { sW1[i] = W1[i]; sRW[i] = rW[i]; }
        if (tid < 128) sRB[tid] = rb[tid];
        __syncthreads();
        int w2 = (blockIdx.x - 1) * 8 + wid;
        for (int row = w2; row < n; row += (NBLK - 1) * 8) {
            float xv = (lane < 20) ? x[(size_t)row * 20 + lane] : 0.f;
            float4 a = make_float4(0.f, 0.f, 0.f, 0.f);
            float4 r = make_float4(0.f, 0.f, 0.f, 0.f);
            #pragma unroll
            for (int k = 0; k < 20; k++) {
                float xk = __shfl_sync(0xffffffffu, xv, k);
                float4 w = ((const float4*)(sW1 + k * 128))[lane];
                a.x += xk * w.x; a.y += xk * w.y; a.z += xk * w.z; a.w += xk * w.w;
                float4 v = ((const float4*)(sRW + k * 128))[lane];
                r.x += xk * v.x; r.y += xk * v.y; r.z += xk * v.z; r.w += xk * v.w;
            }
            float4 rb4 = ((const float4*)sRB)[lane];
            r.x += rb4.x; r.y += rb4.y; r.z += rb4.z; r.w += rb4.w;
            ((float4*)(g_bufA + (size_t)row * HID))[lane] = a;
            ((float4*)(g_res  + (size_t)row * HID))[lane] = r;
        }
    }
    grid_barrier(ls);                                            // B3

    // ---- P3: csr fill ----
    for (int i = gtid; i < e; i += gstr) {
        int s = src[i], d = dst[i];
        int pos = atomicAdd(&g_cursor[d], 1);
        float nrm = rsqrtf((float)(g_deg[s] + 1) * (float)(g_deg[d] + 1));
        g_edge[pos] = make_int2(s, __float_as_int(nrm));
    }
    grid_barrier(ls);                                            // B4

    // ---- layer 1: aggregate + bias + residual + LN + ReLU ----
    agg_ln_phase(g_bufA, g_res, b1, g1, be1, g_hbuf, n, gwarp, lane);
    grid_barrier(ls);                                            // B5

    // ---- layer 2 GEMM ----
    gemm_phase128(g_hbuf, W2, g_bufA, n, sh);
    grid_barrier(ls);                                            // B6

    agg_ln_phase(g_bufA, g_hbuf, b2, g2, be2, g_res, n, gwarp, lane);
    grid_barrier(ls);                                            // B7

    // ---- layer 3: aggregate + pool fused (contiguous chunks, batch sorted) ----
    {
        int ch = (n + NWARP - 1) / NWARP;
        int lo = gwarp * ch;
        int hi = min(n, lo + ch);
        if (lo < hi) {
            float4 pacc = make_float4(0.f, 0.f, 0.f, 0.f);
            int cur = batch[lo];
            for (int node = lo; node < hi; node++) {
                float4 acc = make_float4(0.f, 0.f, 0.f, 0.f);
                gather_node(g_res, node, lane, acc);
                int g = batch[node];
                if (g != cur) {
                    float* p = &g_pool[cur * HID + lane * 4];
                    atomicAdd(p + 0, pacc.x); atomicAdd(p + 1, pacc.y);
                    atomicAdd(p + 2, pacc.z); atomicAdd(p + 3, pacc.w);
                    pacc = make_float4(0.f, 0.f, 0.f, 0.f);
                    cur = g;
                }
                pacc.x += acc.x; pacc.y += acc.y; pacc.z += acc.z; pacc.w += acc.w;
            }
            float* p = &g_pool[cur * HID + lane * 4];
            atomicAdd(p + 0, pacc.x); atomicAdd(p + 1, pacc.y);
            atomicAdd(p + 2, pacc.z); atomicAdd(p + 3, pacc.w);
        }
    }
    grid_barrier(ls);                                            // B8 (even count)

    // ---- final: out[b,:] = (pool[b,:]/cnt[b]) @ W3 + b3 (blocks 0..63) ----
    if (blockIdx.x < NB) {
        int b = blockIdx.x;
        float* sp = sh;               // 128 floats
        float c = (float)g_cnt[b];
        float inv = (c > 0.f) ? 1.f / c : 0.f;
        if (tid < 128) sp[tid] = g_pool[b * HID + tid] * inv;
        __syncthreads();
        float acc = 0.f;
        #pragma unroll 8
        for (int k = 0; k < 128; k++)
            acc += sp[k] * W3[(size_t)k * OUTD + tid];
        out[b * OUTD + tid] = (c > 0.f) ? (acc + b3[tid]) : 0.f;
    }
}

// ---------------------------------------------------------------------------
extern "C" void kernel_launch(void* const* d_in, const int* in_sizes, int n_in,
                              void* d_out, int out_size) {
    const float* x     = (const float*)d_in[0];
    const int*   ei    = (const int*)d_in[1];      // int32 (JAX x64 disabled)
    const int*   batch = (const int*)d_in[2];
    const float *W1 = (const float*)d_in[3],  *b1 = (const float*)d_in[4];
    const float *W2 = (const float*)d_in[5],  *b2 = (const float*)d_in[6];
    const float *W3 = (const float*)d_in[7],  *b3 = (const float*)d_in[8];
    const float *rW = (const float*)d_in[9],  *rb = (const float*)d_in[10];
    const float *g1 = (const float*)d_in[11], *be1 = (const float*)d_in[12];
    const float *g2 = (const float*)d_in[13], *be2 = (const float*)d_in[14];
    float* out = (float*)d_out;

    int n = in_sizes[0] / 20;
    int e = in_sizes[1] / 2;
    const int* src = ei;
    const int* dst = ei + e;

    mega_kernel<<<NBLK, NTHR>>>(x, src, dst, batch,
                                W1, b1, W2, b2, W3, b3, rW, rb,
                                g1, be1, g2, be2, out, n, e);
}